// round 1
// baseline (speedup 1.0000x reference)
#include <cuda_runtime.h>
#include <cuda_bf16.h>
#include <math.h>

// Problem constants
#define B_ 64
#define S_ 100
#define D_ 1024
#define H_ 16
#define F_ 4096
#define DEPTH_ 64
#define BS_ (B_ * S_)          // 6400
#define EPS_ 1e-6f

// ---------------------------------------------------------------------------
// Scratch (device globals; no allocations allowed)
// ---------------------------------------------------------------------------
__device__ float g_pe[S_ * D_];
__device__ float g_x[BS_ * D_];
__device__ float g_WqP[D_ * D_];
__device__ float g_WkP[D_ * D_];
__device__ float g_WvP[D_ * D_];
__device__ float g_Q[BS_ * D_];
__device__ float g_K[BS_ * D_];
__device__ float g_V[BS_ * D_];
__device__ float g_ctx[BS_ * D_];
__device__ float g_t1[BS_ * D_];   // att_out + x  (pre-LN1), reused for pre-LN2
__device__ float g_x1[BS_ * D_];
__device__ float g_ffh[BS_ * F_];

// ---------------------------------------------------------------------------
// Positional encoding (fp64 to match the numpy float64 reference table)
// ---------------------------------------------------------------------------
__global__ void pe_kernel(float* __restrict__ pe) {
    int idx = blockIdx.x * blockDim.x + threadIdx.x;
    if (idx >= S_ * D_) return;
    int s = idx / D_;
    int d = idx % D_;
    int k2 = d & ~1;  // 2*(i//2)
    double div = pow(10000.0, (double)k2 / (double)D_);
    double arg = (double)s / div;
    pe[idx] = (float)((d & 1) ? cos(arg) : sin(arg));
}

// ---------------------------------------------------------------------------
// Embedding gather + positional add
// ---------------------------------------------------------------------------
__global__ void embed_kernel(const int* __restrict__ tokens,
                             const float* __restrict__ emb,
                             const float* __restrict__ pe,
                             float* __restrict__ x) {
    int idx = blockIdx.x * blockDim.x + threadIdx.x;  // over BS_*D_/4
    if (idx >= BS_ * D_ / 4) return;
    int row = idx / (D_ / 4);
    int c4 = idx % (D_ / 4);
    int tok = tokens[row];
    float4 e = ((const float4*)(emb + (size_t)tok * D_))[c4];
    float4 p = ((const float4*)(pe + (size_t)(row % S_) * D_))[c4];
    float4 o;
    o.x = e.x + p.x; o.y = e.y + p.y; o.z = e.z + p.z; o.w = e.w + p.w;
    ((float4*)x)[idx] = o;
}

// ---------------------------------------------------------------------------
// Permute W[H, D, DEPTH] -> Wp[D, H*DEPTH]
// ---------------------------------------------------------------------------
__global__ void permute_w_kernel(const float* __restrict__ W, float* __restrict__ Wp) {
    int idx = blockIdx.x * blockDim.x + threadIdx.x;  // over D_*D_
    if (idx >= D_ * D_) return;
    int d = idx / D_;
    int n = idx % D_;
    int h = n >> 6;
    int e = n & 63;
    Wp[idx] = W[((size_t)h * D_ + d) * DEPTH_ + e];
}

// ---------------------------------------------------------------------------
// SGEMM: C[M,N] = A[M,K] @ B[K,N] (+bias +relu +residual per EPI bitmask)
// EPI bit0 = bias, bit1 = relu, bit2 = residual
// Requires M%128==0, N%128==0, K%8==0.
// ---------------------------------------------------------------------------
#define GBM 128
#define GBN 128
#define GBK 8
#define GTM 8
#define GTN 8

template <int EPI>
__global__ __launch_bounds__(256, 2)
void sgemm_kernel(const float* __restrict__ A, const float* __restrict__ B,
                  float* __restrict__ C, const float* __restrict__ bias,
                  const float* __restrict__ res, int M, int N, int K) {
    __shared__ float As[GBK][GBM];
    __shared__ float Bs[GBK][GBN];

    int tid = threadIdx.x;
    int tx = tid & 15;   // 16 col-groups
    int ty = tid >> 4;   // 16 row-groups
    int blockRow = blockIdx.y * GBM;
    int blockCol = blockIdx.x * GBN;

    int aRow = tid >> 1;          // 0..127
    int aCol = (tid & 1) << 2;    // 0 or 4
    int bRow = tid >> 5;          // 0..7
    int bCol = (tid & 31) << 2;   // 0..124

    const float* Aptr = A + (size_t)(blockRow + aRow) * K + aCol;
    const float* Bptr = B + (size_t)bRow * N + blockCol + bCol;

    float acc[GTM][GTN];
#pragma unroll
    for (int i = 0; i < GTM; i++)
#pragma unroll
        for (int j = 0; j < GTN; j++) acc[i][j] = 0.f;

    float ra[GTM], rb[GTN];

    for (int kk = 0; kk < K; kk += GBK) {
        float4 a4 = *(const float4*)Aptr;
        float4 b4 = *(const float4*)Bptr;
        Aptr += GBK;
        Bptr += (size_t)GBK * N;
        As[aCol + 0][aRow] = a4.x;
        As[aCol + 1][aRow] = a4.y;
        As[aCol + 2][aRow] = a4.z;
        As[aCol + 3][aRow] = a4.w;
        *(float4*)&Bs[bRow][bCol] = b4;
        __syncthreads();
#pragma unroll
        for (int k = 0; k < GBK; k++) {
#pragma unroll
            for (int i = 0; i < GTM; i++) ra[i] = As[k][ty * GTM + i];
#pragma unroll
            for (int j = 0; j < GTN; j++) rb[j] = Bs[k][tx * GTN + j];
#pragma unroll
            for (int i = 0; i < GTM; i++)
#pragma unroll
                for (int j = 0; j < GTN; j++) acc[i][j] += ra[i] * rb[j];
        }
        __syncthreads();
    }

#pragma unroll
    for (int i = 0; i < GTM; i++) {
        int row = blockRow + ty * GTM + i;
#pragma unroll
        for (int j = 0; j < GTN; j += 4) {
            int col = blockCol + tx * GTN + j;
            float4 v;
            v.x = acc[i][j + 0];
            v.y = acc[i][j + 1];
            v.z = acc[i][j + 2];
            v.w = acc[i][j + 3];
            if (EPI & 1) {
                float4 bv = *(const float4*)&bias[col];
                v.x += bv.x; v.y += bv.y; v.z += bv.z; v.w += bv.w;
            }
            if (EPI & 4) {
                float4 rv = *(const float4*)&res[(size_t)row * N + col];
                v.x += rv.x; v.y += rv.y; v.z += rv.z; v.w += rv.w;
            }
            if (EPI & 2) {
                v.x = fmaxf(v.x, 0.f); v.y = fmaxf(v.y, 0.f);
                v.z = fmaxf(v.z, 0.f); v.w = fmaxf(v.w, 0.f);
            }
            *(float4*)&C[(size_t)row * N + col] = v;
        }
    }
}

// ---------------------------------------------------------------------------
// Fused attention per (b, h) block: scores -> softmax -> ctx, all in smem.
// Q/K/V layout: [BS_, D_] with head h at columns [h*64, h*64+64).
// ---------------------------------------------------------------------------
#define ATT_SMEM ((3 * S_ * 65 + S_ * 101) * 4)  // 118400 bytes

__global__ void attention_kernel(const float* __restrict__ Q,
                                 const float* __restrict__ Km,
                                 const float* __restrict__ Vm,
                                 float* __restrict__ ctx) {
    extern __shared__ float sm[];
    float* qs = sm;                 // [S_][65]
    float* ks = qs + S_ * 65;       // [S_][65]
    float* vs = ks + S_ * 65;       // [S_][65]
    float* sc = vs + S_ * 65;       // [S_][101]

    int bh = blockIdx.x;
    int b = bh / H_;
    int h = bh % H_;
    int tid = threadIdx.x;

    const size_t base = (size_t)b * S_ * D_ + (size_t)h * DEPTH_;

    for (int i = tid; i < S_ * DEPTH_; i += blockDim.x) {
        int s = i >> 6, e = i & 63;
        size_t g = base + (size_t)s * D_ + e;
        qs[s * 65 + e] = Q[g];
        ks[s * 65 + e] = Km[g];
        vs[s * 65 + e] = Vm[g];
    }
    __syncthreads();

    const float scale = 0.125f;  // 1/sqrt(64)
    for (int idx = tid; idx < S_ * S_; idx += blockDim.x) {
        int i = idx / S_, j = idx % S_;
        float acc = 0.f;
#pragma unroll
        for (int e = 0; e < DEPTH_; e++) acc += qs[i * 65 + e] * ks[j * 65 + e];
        sc[i * 101 + j] = acc * scale;
    }
    __syncthreads();

    if (tid < S_) {
        int i = tid;
        float m = -1e30f;
        for (int j = 0; j < S_; j++) m = fmaxf(m, sc[i * 101 + j]);
        float sum = 0.f;
        for (int j = 0; j < S_; j++) {
            float e = expf(sc[i * 101 + j] - m);
            sc[i * 101 + j] = e;
            sum += e;
        }
        float inv = 1.f / sum;
        for (int j = 0; j < S_; j++) sc[i * 101 + j] *= inv;
    }
    __syncthreads();

    for (int idx = tid; idx < S_ * DEPTH_; idx += blockDim.x) {
        int i = idx >> 6, e = idx & 63;
        float acc = 0.f;
        for (int j = 0; j < S_; j++) acc += sc[i * 101 + j] * vs[j * 65 + e];
        ctx[base + (size_t)i * D_ + e] = acc;
    }
}

// ---------------------------------------------------------------------------
// LayerNorm over last dim (D_=1024). One block per row; 256 threads, 4 el/thr.
// ---------------------------------------------------------------------------
__global__ __launch_bounds__(256)
void layernorm_kernel(const float* __restrict__ in, const float* __restrict__ gamma,
                      const float* __restrict__ beta, float* __restrict__ out) {
    int row = blockIdx.x;
    const float* p = in + (size_t)row * D_;
    float* o = out + (size_t)row * D_;
    int tid = threadIdx.x;

    float vals[4];
    float sum = 0.f, sq = 0.f;
#pragma unroll
    for (int r = 0; r < 4; r++) {
        float v = p[tid + r * 256];
        vals[r] = v;
        sum += v;
        sq += v * v;
    }
    // warp reduce
#pragma unroll
    for (int off = 16; off > 0; off >>= 1) {
        sum += __shfl_xor_sync(0xffffffffu, sum, off);
        sq += __shfl_xor_sync(0xffffffffu, sq, off);
    }
    __shared__ float s1[8], s2[8];
    int wid = tid >> 5, lid = tid & 31;
    if (lid == 0) { s1[wid] = sum; s2[wid] = sq; }
    __syncthreads();
    if (wid == 0) {
        sum = (lid < 8) ? s1[lid] : 0.f;
        sq = (lid < 8) ? s2[lid] : 0.f;
#pragma unroll
        for (int off = 4; off > 0; off >>= 1) {
            sum += __shfl_xor_sync(0xffffffffu, sum, off);
            sq += __shfl_xor_sync(0xffffffffu, sq, off);
        }
        if (lid == 0) { s1[0] = sum; s2[0] = sq; }
    }
    __syncthreads();
    float mean = s1[0] * (1.0f / D_);
    float var = s2[0] * (1.0f / D_) - mean * mean;
    float inv = rsqrtf(var + EPS_);
#pragma unroll
    for (int r = 0; r < 4; r++) {
        int d = tid + r * 256;
        o[d] = gamma[d] * ((vals[r] - mean) * inv) + beta[d];
    }
}

// ---------------------------------------------------------------------------
// Launch
// ---------------------------------------------------------------------------
static inline void get_sym(void** p, const void* sym) {
    cudaGetSymbolAddress(p, sym);
}

extern "C" void kernel_launch(void* const* d_in, const int* in_sizes, int n_in,
                              void* d_out, int out_size) {
    const int* tokens = (const int*)d_in[0];
    const float* emb = (const float*)d_in[1];
    const float* Wq = (const float*)d_in[2];
    const float* bq = (const float*)d_in[3];
    const float* Wk = (const float*)d_in[4];
    const float* bk = (const float*)d_in[5];
    const float* Wv = (const float*)d_in[6];
    const float* bv = (const float*)d_in[7];
    const float* Wo = (const float*)d_in[8];
    const float* bo = (const float*)d_in[9];
    const float* W1 = (const float*)d_in[10];
    const float* b1 = (const float*)d_in[11];
    const float* W2 = (const float*)d_in[12];
    const float* b2 = (const float*)d_in[13];
    const float* gamma1 = (const float*)d_in[14];
    const float* beta1 = (const float*)d_in[15];
    const float* gamma2 = (const float*)d_in[16];
    const float* beta2 = (const float*)d_in[17];
    float* out = (float*)d_out;

    float *pe, *x, *WqP, *WkP, *WvP, *Qp, *Kp, *Vp, *ctx, *t1, *x1, *ffh;
    cudaGetSymbolAddress((void**)&pe, g_pe);
    cudaGetSymbolAddress((void**)&x, g_x);
    cudaGetSymbolAddress((void**)&WqP, g_WqP);
    cudaGetSymbolAddress((void**)&WkP, g_WkP);
    cudaGetSymbolAddress((void**)&WvP, g_WvP);
    cudaGetSymbolAddress((void**)&Qp, g_Q);
    cudaGetSymbolAddress((void**)&Kp, g_K);
    cudaGetSymbolAddress((void**)&Vp, g_V);
    cudaGetSymbolAddress((void**)&ctx, g_ctx);
    cudaGetSymbolAddress((void**)&t1, g_t1);
    cudaGetSymbolAddress((void**)&x1, g_x1);
    cudaGetSymbolAddress((void**)&ffh, g_ffh);

    cudaFuncSetAttribute(attention_kernel,
                         cudaFuncAttributeMaxDynamicSharedMemorySize, ATT_SMEM);

    // 1. positional encoding + embedding
    pe_kernel<<<(S_ * D_ + 255) / 256, 256>>>(pe);
    embed_kernel<<<(BS_ * D_ / 4 + 255) / 256, 256>>>(tokens, emb, pe, x);

    // 2. weight permutes
    permute_w_kernel<<<(D_ * D_ + 255) / 256, 256>>>(Wq, WqP);
    permute_w_kernel<<<(D_ * D_ + 255) / 256, 256>>>(Wk, WkP);
    permute_w_kernel<<<(D_ * D_ + 255) / 256, 256>>>(Wv, WvP);

    // 3. QKV projections (bias vectors bq/bk/bv are already [H*DEPTH] flat)
    {
        dim3 grid(D_ / GBN, BS_ / GBM);
        sgemm_kernel<1><<<grid, 256>>>(x, WqP, Qp, bq, nullptr, BS_, D_, D_);
        sgemm_kernel<1><<<grid, 256>>>(x, WkP, Kp, bk, nullptr, BS_, D_, D_);
        sgemm_kernel<1><<<grid, 256>>>(x, WvP, Vp, bv, nullptr, BS_, D_, D_);
    }

    // 4. attention
    attention_kernel<<<B_ * H_, 256, ATT_SMEM>>>(Qp, Kp, Vp, ctx);

    // 5. output projection + residual, LN1
    {
        dim3 grid(D_ / GBN, BS_ / GBM);
        sgemm_kernel<5><<<grid, 256>>>(ctx, Wo, t1, bo, x, BS_, D_, D_);
    }
    layernorm_kernel<<<BS_, 256>>>(t1, gamma1, beta1, x1);

    // 6. FFN
    {
        dim3 grid1(F_ / GBN, BS_ / GBM);
        sgemm_kernel<3><<<grid1, 256>>>(x1, W1, ffh, b1, nullptr, BS_, F_, D_);
        dim3 grid2(D_ / GBN, BS_ / GBM);
        sgemm_kernel<5><<<grid2, 256>>>(ffh, W2, t1, b2, x1, BS_, D_, F_);
    }

    // 7. LN2 -> output
    layernorm_kernel<<<BS_, 256>>>(t1, gamma2, beta2, out);
}

// round 2
// speedup vs baseline: 3.3488x; 3.3488x over previous
#include <cuda_runtime.h>
#include <cuda_bf16.h>
#include <math.h>
#include <stdint.h>

// Problem constants
#define B_ 64
#define S_ 100
#define D_ 1024
#define H_ 16
#define F_ 4096
#define DEPTH_ 64
#define BS_ (B_ * S_)          // 6400
#define N_QKV 3072
#define EPS_ 1e-6f

// ---------------------------------------------------------------------------
// Scratch (device globals; no allocations allowed)
// ---------------------------------------------------------------------------
__device__ float g_pe[S_ * D_];
__device__ float g_x[BS_ * D_];
__device__ float g_Wqkv[D_ * N_QKV];
__device__ float g_bqkv[N_QKV];
__device__ float g_QKV[BS_ * N_QKV];
__device__ float g_ctx[BS_ * D_];
__device__ float g_t1[BS_ * D_];   // pre-LN1, reused for pre-LN2
__device__ float g_x1[BS_ * D_];
__device__ float g_ffh[BS_ * F_];

// ---------------------------------------------------------------------------
// Positional encoding (fp64 to match the numpy float64 reference table)
// ---------------------------------------------------------------------------
__global__ void pe_kernel(float* __restrict__ pe) {
    int idx = blockIdx.x * blockDim.x + threadIdx.x;
    if (idx >= S_ * D_) return;
    int s = idx / D_;
    int d = idx % D_;
    int k2 = d & ~1;
    double div = pow(10000.0, (double)k2 / (double)D_);
    double arg = (double)s / div;
    pe[idx] = (float)((d & 1) ? cos(arg) : sin(arg));
}

// ---------------------------------------------------------------------------
// Embedding gather + positional add
// ---------------------------------------------------------------------------
__global__ void embed_kernel(const int* __restrict__ tokens,
                             const float* __restrict__ emb,
                             const float* __restrict__ pe,
                             float* __restrict__ x) {
    int idx = blockIdx.x * blockDim.x + threadIdx.x;
    if (idx >= BS_ * D_ / 4) return;
    int row = idx / (D_ / 4);
    int c4 = idx % (D_ / 4);
    int tok = tokens[row];
    float4 e = ((const float4*)(emb + (size_t)tok * D_))[c4];
    float4 p = ((const float4*)(pe + (size_t)(row % S_) * D_))[c4];
    float4 o;
    o.x = e.x + p.x; o.y = e.y + p.y; o.z = e.z + p.z; o.w = e.w + p.w;
    ((float4*)x)[idx] = o;
}

// ---------------------------------------------------------------------------
// Permute Wq/Wk/Wv [H,D,64] -> combined [D, 3072]; concat biases -> [3072]
// ---------------------------------------------------------------------------
__global__ void permute_qkv_kernel(const float* __restrict__ Wq, const float* __restrict__ Wk,
                                   const float* __restrict__ Wv,
                                   const float* __restrict__ bq, const float* __restrict__ bk,
                                   const float* __restrict__ bv,
                                   float* __restrict__ Wout, float* __restrict__ bout) {
    int idx = blockIdx.x * blockDim.x + threadIdx.x;
    const int total = 3 * D_ * D_;
    if (idx < total) {
        int which = idx / (D_ * D_);
        int r = idx % (D_ * D_);
        int d = r / D_;
        int n = r % D_;
        int h = n >> 6, e = n & 63;
        const float* W = (which == 0) ? Wq : ((which == 1) ? Wk : Wv);
        Wout[(size_t)d * N_QKV + which * D_ + n] = W[((size_t)h * D_ + d) * DEPTH_ + e];
    }
    if (idx < N_QKV) {
        int which = idx / D_;
        int n = idx % D_;
        const float* bb = (which == 0) ? bq : ((which == 1) ? bk : bv);
        bout[idx] = bb[n];
    }
}

// ---------------------------------------------------------------------------
// TF32 tensor-core GEMM: C[M,N] = A[M,K] @ B[K,N] (+bias/relu/residual)
// 128x128 CTA tile, K-step 32, 8 warps of 32x64 warp tiles,
// cp.async 2-stage pipeline, conflict-free smem strides.
// EPI: bit0 = bias, bit1 = relu, bit2 = residual.
// Requires M%128==0, N%128==0, K%32==0.
// ---------------------------------------------------------------------------
#define ASTRIDE 44                   // floats per A row in smem (16B-aligned rows)
#define BSTRIDE 136                  // floats per B row in smem
#define AFLOATS (128 * ASTRIDE)      // 5632
#define BFLOATS (32 * BSTRIDE)       // 4352
#define STAGEF  (AFLOATS + BFLOATS)  // 9984 floats
#define SMEM_GEMM (2 * STAGEF * 4)   // 79872 bytes

__device__ __forceinline__ uint32_t f2tf32(float x) {
    uint32_t r;
    asm("cvt.rna.tf32.f32 %0, %1;" : "=r"(r) : "f"(x));
    return r;
}

__device__ __forceinline__ void mma_tf32(float* d, const uint32_t* a, const uint32_t* b) {
    asm volatile(
        "mma.sync.aligned.m16n8k8.row.col.f32.tf32.tf32.f32 "
        "{%0,%1,%2,%3}, {%4,%5,%6,%7}, {%8,%9}, {%0,%1,%2,%3};\n"
        : "+f"(d[0]), "+f"(d[1]), "+f"(d[2]), "+f"(d[3])
        : "r"(a[0]), "r"(a[1]), "r"(a[2]), "r"(a[3]), "r"(b[0]), "r"(b[1]));
}

template <int EPI>
__global__ __launch_bounds__(256, 2)
void mma_gemm(const float* __restrict__ A, const float* __restrict__ Bm,
              float* __restrict__ C, const float* __restrict__ bias,
              const float* __restrict__ res, int M, int N, int K) {
    extern __shared__ float smf[];
    int tid = threadIdx.x;
    int lane = tid & 31, warp = tid >> 5;
    int wm = warp & 3, wn = warp >> 2;     // 4x2 warp grid
    int g = lane >> 2, tg = lane & 3;
    int bm = blockIdx.y * 128, bn = blockIdx.x * 128;

    uint32_t smemBase = (uint32_t)__cvta_generic_to_shared(smf);

    float acc[2][8][4];
#pragma unroll
    for (int i = 0; i < 2; i++)
#pragma unroll
        for (int j = 0; j < 8; j++)
#pragma unroll
            for (int c = 0; c < 4; c++) acc[i][j][c] = 0.f;

    const int KT = K / 32;

    auto prefetch = [&](int kt, int stage) {
        uint32_t sA = smemBase + (uint32_t)(stage * STAGEF * 4);
        uint32_t sB = sA + AFLOATS * 4;
        const float* gA = A + (size_t)bm * K + (size_t)kt * 32;
        const float* gB = Bm + (size_t)kt * 32 * N + bn;
#pragma unroll
        for (int q = 0; q < 4; q++) {
            int lin = tid + q * 256;
            int row = lin >> 3, colv = lin & 7;
            uint32_t dst = sA + (uint32_t)(row * ASTRIDE + colv * 4) * 4;
            const float* src = gA + (size_t)row * K + colv * 4;
            asm volatile("cp.async.cg.shared.global [%0], [%1], 16;" :: "r"(dst), "l"(src));
        }
#pragma unroll
        for (int q = 0; q < 4; q++) {
            int lin = tid + q * 256;
            int krow = lin >> 5, colv = lin & 31;
            uint32_t dst = sB + (uint32_t)(krow * BSTRIDE + colv * 4) * 4;
            const float* src = gB + (size_t)krow * N + colv * 4;
            asm volatile("cp.async.cg.shared.global [%0], [%1], 16;" :: "r"(dst), "l"(src));
        }
    };

    prefetch(0, 0);
    asm volatile("cp.async.commit_group;");

    for (int kt = 0; kt < KT; kt++) {
        if (kt + 1 < KT) prefetch(kt + 1, (kt + 1) & 1);
        asm volatile("cp.async.commit_group;");
        asm volatile("cp.async.wait_group 1;");
        __syncthreads();

        const float* As = smf + (kt & 1) * STAGEF;
        const float* Bs = As + AFLOATS;
#pragma unroll
        for (int ks = 0; ks < 4; ks++) {
            int k0 = ks * 8;
            uint32_t afr[2][4];
#pragma unroll
            for (int mi = 0; mi < 2; mi++) {
                int m = wm * 32 + mi * 16 + g;
                afr[mi][0] = f2tf32(As[m * ASTRIDE + k0 + tg]);
                afr[mi][1] = f2tf32(As[(m + 8) * ASTRIDE + k0 + tg]);
                afr[mi][2] = f2tf32(As[m * ASTRIDE + k0 + tg + 4]);
                afr[mi][3] = f2tf32(As[(m + 8) * ASTRIDE + k0 + tg + 4]);
            }
            uint32_t bfr[8][2];
#pragma unroll
            for (int ni = 0; ni < 8; ni++) {
                int n = wn * 64 + ni * 8 + g;
                bfr[ni][0] = f2tf32(Bs[(k0 + tg) * BSTRIDE + n]);
                bfr[ni][1] = f2tf32(Bs[(k0 + tg + 4) * BSTRIDE + n]);
            }
#pragma unroll
            for (int mi = 0; mi < 2; mi++)
#pragma unroll
                for (int ni = 0; ni < 8; ni++)
                    mma_tf32(acc[mi][ni], afr[mi], bfr[ni]);
        }
        __syncthreads();
    }

    // Epilogue: each (mi, ni) frag holds rows {r, r+8}, cols {c, c+1}
#pragma unroll
    for (int mi = 0; mi < 2; mi++) {
#pragma unroll
        for (int rr = 0; rr < 2; rr++) {
            int row = bm + wm * 32 + mi * 16 + rr * 8 + g;
#pragma unroll
            for (int ni = 0; ni < 8; ni++) {
                int col = bn + wn * 64 + ni * 8 + tg * 2;
                float vx = acc[mi][ni][rr * 2 + 0];
                float vy = acc[mi][ni][rr * 2 + 1];
                if (EPI & 1) { vx += bias[col]; vy += bias[col + 1]; }
                if (EPI & 4) {
                    const float* rp = res + (size_t)row * N + col;
                    vx += rp[0]; vy += rp[1];
                }
                if (EPI & 2) { vx = fmaxf(vx, 0.f); vy = fmaxf(vy, 0.f); }
                float2 o = make_float2(vx, vy);
                *(float2*)&C[(size_t)row * N + col] = o;
            }
        }
    }
}

// ---------------------------------------------------------------------------
// Fused attention per (b, h): reads combined QKV buffer [BS, 3072].
// ---------------------------------------------------------------------------
#define ATT_SMEM ((3 * S_ * 65 + S_ * 101) * 4)  // 118400 bytes

__global__ void attention_kernel(const float* __restrict__ QKV,
                                 float* __restrict__ ctx) {
    extern __shared__ float sm[];
    float* qs = sm;                 // [S_][65]
    float* ks = qs + S_ * 65;
    float* vs = ks + S_ * 65;
    float* sc = vs + S_ * 65;       // [S_][101]

    int bh = blockIdx.x;
    int b = bh / H_;
    int h = bh % H_;
    int tid = threadIdx.x;

    for (int i = tid; i < S_ * DEPTH_; i += blockDim.x) {
        int s = i >> 6, e = i & 63;
        size_t off = ((size_t)(b * S_ + s)) * N_QKV + h * DEPTH_ + e;
        qs[s * 65 + e] = QKV[off];
        ks[s * 65 + e] = QKV[off + D_];
        vs[s * 65 + e] = QKV[off + 2 * D_];
    }
    __syncthreads();

    const float scale = 0.125f;  // 1/sqrt(64)
    for (int idx = tid; idx < S_ * S_; idx += blockDim.x) {
        int i = idx / S_, j = idx % S_;
        float acc = 0.f;
#pragma unroll
        for (int e = 0; e < DEPTH_; e++) acc += qs[i * 65 + e] * ks[j * 65 + e];
        sc[i * 101 + j] = acc * scale;
    }
    __syncthreads();

    if (tid < S_) {
        int i = tid;
        float m = -1e30f;
        for (int j = 0; j < S_; j++) m = fmaxf(m, sc[i * 101 + j]);
        float sum = 0.f;
        for (int j = 0; j < S_; j++) {
            float e = expf(sc[i * 101 + j] - m);
            sc[i * 101 + j] = e;
            sum += e;
        }
        float inv = 1.f / sum;
        for (int j = 0; j < S_; j++) sc[i * 101 + j] *= inv;
    }
    __syncthreads();

    const size_t cbase = (size_t)b * S_ * D_ + (size_t)h * DEPTH_;
    for (int idx = tid; idx < S_ * DEPTH_; idx += blockDim.x) {
        int i = idx >> 6, e = idx & 63;
        float acc = 0.f;
        for (int j = 0; j < S_; j++) acc += sc[i * 101 + j] * vs[j * 65 + e];
        ctx[cbase + (size_t)i * D_ + e] = acc;
    }
}

// ---------------------------------------------------------------------------
// LayerNorm over last dim (D_=1024). One block per row.
// ---------------------------------------------------------------------------
__global__ __launch_bounds__(256)
void layernorm_kernel(const float* __restrict__ in, const float* __restrict__ gamma,
                      const float* __restrict__ beta, float* __restrict__ out) {
    int row = blockIdx.x;
    const float* p = in + (size_t)row * D_;
    float* o = out + (size_t)row * D_;
    int tid = threadIdx.x;

    float vals[4];
    float sum = 0.f, sq = 0.f;
#pragma unroll
    for (int r = 0; r < 4; r++) {
        float v = p[tid + r * 256];
        vals[r] = v;
        sum += v;
        sq += v * v;
    }
#pragma unroll
    for (int off = 16; off > 0; off >>= 1) {
        sum += __shfl_xor_sync(0xffffffffu, sum, off);
        sq += __shfl_xor_sync(0xffffffffu, sq, off);
    }
    __shared__ float s1[8], s2[8];
    int wid = tid >> 5, lid = tid & 31;
    if (lid == 0) { s1[wid] = sum; s2[wid] = sq; }
    __syncthreads();
    if (wid == 0) {
        sum = (lid < 8) ? s1[lid] : 0.f;
        sq = (lid < 8) ? s2[lid] : 0.f;
#pragma unroll
        for (int off = 4; off > 0; off >>= 1) {
            sum += __shfl_xor_sync(0xffffffffu, sum, off);
            sq += __shfl_xor_sync(0xffffffffu, sq, off);
        }
        if (lid == 0) { s1[0] = sum; s2[0] = sq; }
    }
    __syncthreads();
    float mean = s1[0] * (1.0f / D_);
    float var = s2[0] * (1.0f / D_) - mean * mean;
    float inv = rsqrtf(var + EPS_);
#pragma unroll
    for (int r = 0; r < 4; r++) {
        int d = tid + r * 256;
        o[d] = gamma[d] * ((vals[r] - mean) * inv) + beta[d];
    }
}

// ---------------------------------------------------------------------------
// Launch
// ---------------------------------------------------------------------------
extern "C" void kernel_launch(void* const* d_in, const int* in_sizes, int n_in,
                              void* d_out, int out_size) {
    const int* tokens = (const int*)d_in[0];
    const float* emb = (const float*)d_in[1];
    const float* Wq = (const float*)d_in[2];
    const float* bq = (const float*)d_in[3];
    const float* Wk = (const float*)d_in[4];
    const float* bk = (const float*)d_in[5];
    const float* Wv = (const float*)d_in[6];
    const float* bv = (const float*)d_in[7];
    const float* Wo = (const float*)d_in[8];
    const float* bo = (const float*)d_in[9];
    const float* W1 = (const float*)d_in[10];
    const float* b1 = (const float*)d_in[11];
    const float* W2 = (const float*)d_in[12];
    const float* b2 = (const float*)d_in[13];
    const float* gamma1 = (const float*)d_in[14];
    const float* beta1 = (const float*)d_in[15];
    const float* gamma2 = (const float*)d_in[16];
    const float* beta2 = (const float*)d_in[17];
    float* out = (float*)d_out;

    float *pe, *x, *Wqkv, *bqkv, *QKV, *ctx, *t1, *x1, *ffh;
    cudaGetSymbolAddress((void**)&pe, g_pe);
    cudaGetSymbolAddress((void**)&x, g_x);
    cudaGetSymbolAddress((void**)&Wqkv, g_Wqkv);
    cudaGetSymbolAddress((void**)&bqkv, g_bqkv);
    cudaGetSymbolAddress((void**)&QKV, g_QKV);
    cudaGetSymbolAddress((void**)&ctx, g_ctx);
    cudaGetSymbolAddress((void**)&t1, g_t1);
    cudaGetSymbolAddress((void**)&x1, g_x1);
    cudaGetSymbolAddress((void**)&ffh, g_ffh);

    cudaFuncSetAttribute(attention_kernel,
                         cudaFuncAttributeMaxDynamicSharedMemorySize, ATT_SMEM);
    cudaFuncSetAttribute(mma_gemm<1>,
                         cudaFuncAttributeMaxDynamicSharedMemorySize, SMEM_GEMM);
    cudaFuncSetAttribute(mma_gemm<3>,
                         cudaFuncAttributeMaxDynamicSharedMemorySize, SMEM_GEMM);
    cudaFuncSetAttribute(mma_gemm<5>,
                         cudaFuncAttributeMaxDynamicSharedMemorySize, SMEM_GEMM);

    // 1. positional encoding + embedding
    pe_kernel<<<(S_ * D_ + 255) / 256, 256>>>(pe);
    embed_kernel<<<(BS_ * D_ / 4 + 255) / 256, 256>>>(tokens, emb, pe, x);

    // 2. combined QKV weight permute + bias concat
    permute_qkv_kernel<<<(3 * D_ * D_ + 255) / 256, 256>>>(Wq, Wk, Wv, bq, bk, bv,
                                                           Wqkv, bqkv);

    // 3. fused QKV projection: [6400,1024] @ [1024,3072]
    mma_gemm<1><<<dim3(N_QKV / 128, BS_ / 128), 256, SMEM_GEMM>>>(
        x, Wqkv, QKV, bqkv, nullptr, BS_, N_QKV, D_);

    // 4. attention
    attention_kernel<<<B_ * H_, 256, ATT_SMEM>>>(QKV, ctx);

    // 5. output projection + residual, LN1
    mma_gemm<5><<<dim3(D_ / 128, BS_ / 128), 256, SMEM_GEMM>>>(
        ctx, Wo, t1, bo, x, BS_, D_, D_);
    layernorm_kernel<<<BS_, 256>>>(t1, gamma1, beta1, x1);

    // 6. FFN
    mma_gemm<3><<<dim3(F_ / 128, BS_ / 128), 256, SMEM_GEMM>>>(
        x1, W1, ffh, b1, nullptr, BS_, F_, D_);
    mma_gemm<5><<<dim3(D_ / 128, BS_ / 128), 256, SMEM_GEMM>>>(
        ffh, W2, t1, b2, x1, BS_, D_, F_);

    // 7. LN2 -> output
    layernorm_kernel<<<BS_, 256>>>(t1, gamma2, beta2, out);
}

// round 3
// speedup vs baseline: 3.9035x; 1.1657x over previous
#include <cuda_runtime.h>
#include <cuda_bf16.h>
#include <math.h>
#include <stdint.h>

// Problem constants
#define B_ 64
#define S_ 100
#define D_ 1024
#define H_ 16
#define F_ 4096
#define DEPTH_ 64
#define BS_ (B_ * S_)          // 6400
#define N_QKV 3072
#define EPS_ 1e-6f

// ---------------------------------------------------------------------------
// Scratch (device globals; no allocations allowed)
// ---------------------------------------------------------------------------
__device__ float g_pe[S_ * D_];
__device__ float g_x[BS_ * D_];      // full fp32 (residual path)
__device__ float g_xr[BS_ * D_];     // tf32-rounded (GEMM A operand)
__device__ float g_Wqkv[D_ * N_QKV]; // rounded
__device__ float g_bqkv[N_QKV];
__device__ float g_Wor[D_ * D_];     // rounded Wo
__device__ float g_W1r[D_ * F_];     // rounded W1
__device__ float g_W2r[F_ * D_];     // rounded W2
__device__ float g_QKV[BS_ * N_QKV];
__device__ float g_ctx[BS_ * D_];    // rounded at attention epilogue
__device__ float g_t1[BS_ * D_];     // pre-LN buffers (fp32)
__device__ float g_x1[BS_ * D_];     // fp32
__device__ float g_x1r[BS_ * D_];    // rounded twin
__device__ float g_ffh[BS_ * F_];    // rounded at relu epilogue

__device__ __forceinline__ uint32_t f2tf32(float x) {
    uint32_t r;
    asm("cvt.rna.tf32.f32 %0, %1;" : "=r"(r) : "f"(x));
    return r;
}
__device__ __forceinline__ float roundtf(float x) {
    return __uint_as_float(f2tf32(x));
}

// ---------------------------------------------------------------------------
// Positional encoding (fp64 to match numpy float64 table)
// ---------------------------------------------------------------------------
__global__ void pe_kernel(float* __restrict__ pe) {
    int idx = blockIdx.x * blockDim.x + threadIdx.x;
    if (idx >= S_ * D_) return;
    int s = idx / D_;
    int d = idx % D_;
    int k2 = d & ~1;
    double div = pow(10000.0, (double)k2 / (double)D_);
    double arg = (double)s / div;
    pe[idx] = (float)((d & 1) ? cos(arg) : sin(arg));
}

// ---------------------------------------------------------------------------
// Embedding gather + positional add; writes fp32 x and tf32-rounded xr
// ---------------------------------------------------------------------------
__global__ void embed_kernel(const int* __restrict__ tokens,
                             const float* __restrict__ emb,
                             const float* __restrict__ pe,
                             float* __restrict__ x, float* __restrict__ xr) {
    int idx = blockIdx.x * blockDim.x + threadIdx.x;
    if (idx >= BS_ * D_ / 4) return;
    int row = idx / (D_ / 4);
    int c4 = idx % (D_ / 4);
    int tok = tokens[row];
    float4 e = ((const float4*)(emb + (size_t)tok * D_))[c4];
    float4 p = ((const float4*)(pe + (size_t)(row % S_) * D_))[c4];
    float4 o;
    o.x = e.x + p.x; o.y = e.y + p.y; o.z = e.z + p.z; o.w = e.w + p.w;
    ((float4*)x)[idx] = o;
    float4 r;
    r.x = roundtf(o.x); r.y = roundtf(o.y); r.z = roundtf(o.z); r.w = roundtf(o.w);
    ((float4*)xr)[idx] = r;
}

// ---------------------------------------------------------------------------
// Permute Wq/Wk/Wv [H,D,64] -> combined [D, 3072] (tf32-rounded); biases -> [3072]
// ---------------------------------------------------------------------------
__global__ void permute_qkv_kernel(const float* __restrict__ Wq, const float* __restrict__ Wk,
                                   const float* __restrict__ Wv,
                                   const float* __restrict__ bq, const float* __restrict__ bk,
                                   const float* __restrict__ bv,
                                   float* __restrict__ Wout, float* __restrict__ bout) {
    int idx = blockIdx.x * blockDim.x + threadIdx.x;
    const int total = 3 * D_ * D_;
    if (idx < total) {
        int which = idx / (D_ * D_);
        int r = idx % (D_ * D_);
        int d = r / D_;
        int n = r % D_;
        int h = n >> 6, e = n & 63;
        const float* W = (which == 0) ? Wq : ((which == 1) ? Wk : Wv);
        Wout[(size_t)d * N_QKV + which * D_ + n] =
            roundtf(W[((size_t)h * D_ + d) * DEPTH_ + e]);
    }
    if (idx < N_QKV) {
        int which = idx / D_;
        int n = idx % D_;
        const float* bb = (which == 0) ? bq : ((which == 1) ? bk : bv);
        bout[idx] = bb[n];
    }
}

// ---------------------------------------------------------------------------
// tf32 round-copy (for raw weight inputs used as B operands)
// ---------------------------------------------------------------------------
__global__ void roundcpy_kernel(const float* __restrict__ in, float* __restrict__ out, int n4) {
    int idx = blockIdx.x * blockDim.x + threadIdx.x;
    if (idx >= n4) return;
    float4 v = ((const float4*)in)[idx];
    float4 r;
    r.x = roundtf(v.x); r.y = roundtf(v.y); r.z = roundtf(v.z); r.w = roundtf(v.w);
    ((float4*)out)[idx] = r;
}

// ---------------------------------------------------------------------------
// TF32 tensor-core GEMM (inputs pre-rounded; no cvt in mainloop).
// 128x128 CTA tile, k-step 32, 8 warps (32x64), cp.async double buffer.
// EPI: bit0 bias, bit1 relu, bit2 residual, bit3 round-output.
// ---------------------------------------------------------------------------
#define ASTRIDE 44
#define BSTRIDE 136
#define AFLOATS (128 * ASTRIDE)
#define BFLOATS (32 * BSTRIDE)
#define STAGEF  (AFLOATS + BFLOATS)
#define SMEM_GEMM (2 * STAGEF * 4)

__device__ __forceinline__ void mma_tf32(float* d, const uint32_t* a, const uint32_t* b) {
    asm volatile(
        "mma.sync.aligned.m16n8k8.row.col.f32.tf32.tf32.f32 "
        "{%0,%1,%2,%3}, {%4,%5,%6,%7}, {%8,%9}, {%0,%1,%2,%3};\n"
        : "+f"(d[0]), "+f"(d[1]), "+f"(d[2]), "+f"(d[3])
        : "r"(a[0]), "r"(a[1]), "r"(a[2]), "r"(a[3]), "r"(b[0]), "r"(b[1]));
}

template <int EPI>
__global__ __launch_bounds__(256, 2)
void mma_gemm(const float* __restrict__ A, const float* __restrict__ Bm,
              float* __restrict__ C, const float* __restrict__ bias,
              const float* __restrict__ res, int M, int N, int K) {
    extern __shared__ float smf[];
    int tid = threadIdx.x;
    int lane = tid & 31, warp = tid >> 5;
    int wm = warp & 3, wn = warp >> 2;
    int g = lane >> 2, tg = lane & 3;
    int bm = blockIdx.y * 128, bn = blockIdx.x * 128;

    uint32_t smemBase = (uint32_t)__cvta_generic_to_shared(smf);

    float acc[2][8][4];
#pragma unroll
    for (int i = 0; i < 2; i++)
#pragma unroll
        for (int j = 0; j < 8; j++)
#pragma unroll
            for (int c = 0; c < 4; c++) acc[i][j][c] = 0.f;

    const int KT = K / 32;

    // Pointer-carried prefetch state (addresses computed once)
    int aRow = tid >> 3, aColv = tid & 7;       // 128 rows x 8 float4
    int bKrow = tid >> 5, bColv = tid & 31;     // 8 krows x 32 float4 (x4 reps)
    const float* aSrc = A + (size_t)(bm + aRow) * K + aColv * 4;
    const float* bSrc = Bm + (size_t)bKrow * N + bn + bColv * 4;
    uint32_t aDst0 = smemBase + (uint32_t)(aRow * ASTRIDE + aColv * 4) * 4;
    uint32_t bDst0 = smemBase + AFLOATS * 4 + (uint32_t)(bKrow * BSTRIDE + bColv * 4) * 4;
    const size_t bStepRep = (size_t)8 * N;      // 8 k-rows per rep

    auto prefetch = [&](int stage) {
        uint32_t so = (uint32_t)(stage * STAGEF * 4);
#pragma unroll
        for (int q = 0; q < 4; q++) {
            uint32_t dst = aDst0 + so + (uint32_t)(q * 32 * ASTRIDE) * 4;
            const float* src = aSrc + (size_t)(q * 32) * K;
            asm volatile("cp.async.cg.shared.global [%0], [%1], 16;" :: "r"(dst), "l"(src));
        }
#pragma unroll
        for (int q = 0; q < 4; q++) {
            uint32_t dst = bDst0 + so + (uint32_t)(q * 8 * BSTRIDE) * 4;
            const float* src = bSrc + (size_t)q * bStepRep;
            asm volatile("cp.async.cg.shared.global [%0], [%1], 16;" :: "r"(dst), "l"(src));
        }
        aSrc += 32;
        bSrc += (size_t)32 * N;
    };

    prefetch(0);
    asm volatile("cp.async.commit_group;");

    for (int kt = 0; kt < KT; kt++) {
        if (kt + 1 < KT) prefetch((kt + 1) & 1);
        asm volatile("cp.async.commit_group;");
        asm volatile("cp.async.wait_group 1;");
        __syncthreads();

        const uint32_t* As = (const uint32_t*)(smf + (kt & 1) * STAGEF);
        const uint32_t* Bs = As + AFLOATS;
#pragma unroll
        for (int ks = 0; ks < 4; ks++) {
            int k0 = ks * 8;
            uint32_t afr[2][4];
#pragma unroll
            for (int mi = 0; mi < 2; mi++) {
                int m = wm * 32 + mi * 16 + g;
                afr[mi][0] = As[m * ASTRIDE + k0 + tg];
                afr[mi][1] = As[(m + 8) * ASTRIDE + k0 + tg];
                afr[mi][2] = As[m * ASTRIDE + k0 + tg + 4];
                afr[mi][3] = As[(m + 8) * ASTRIDE + k0 + tg + 4];
            }
            uint32_t bfr[8][2];
#pragma unroll
            for (int ni = 0; ni < 8; ni++) {
                int n = wn * 64 + ni * 8 + g;
                bfr[ni][0] = Bs[(k0 + tg) * BSTRIDE + n];
                bfr[ni][1] = Bs[(k0 + tg + 4) * BSTRIDE + n];
            }
#pragma unroll
            for (int mi = 0; mi < 2; mi++)
#pragma unroll
                for (int ni = 0; ni < 8; ni++)
                    mma_tf32(acc[mi][ni], afr[mi], bfr[ni]);
        }
        __syncthreads();
    }

#pragma unroll
    for (int mi = 0; mi < 2; mi++) {
#pragma unroll
        for (int rr = 0; rr < 2; rr++) {
            int row = bm + wm * 32 + mi * 16 + rr * 8 + g;
#pragma unroll
            for (int ni = 0; ni < 8; ni++) {
                int col = bn + wn * 64 + ni * 8 + tg * 2;
                float vx = acc[mi][ni][rr * 2 + 0];
                float vy = acc[mi][ni][rr * 2 + 1];
                if (EPI & 1) { vx += bias[col]; vy += bias[col + 1]; }
                if (EPI & 4) {
                    const float* rp = res + (size_t)row * N + col;
                    vx += rp[0]; vy += rp[1];
                }
                if (EPI & 2) { vx = fmaxf(vx, 0.f); vy = fmaxf(vy, 0.f); }
                if (EPI & 8) { vx = roundtf(vx); vy = roundtf(vy); }
                *(float2*)&C[(size_t)row * N + col] = make_float2(vx, vy);
            }
        }
    }
}

// ---------------------------------------------------------------------------
// Fused attention per (b, h). Register-tiled QK (4x4), transposed K in smem,
// warp-parallel softmax, float4 AV. Output rounded to tf32 (GEMM A operand).
// ---------------------------------------------------------------------------
#define QS_STR 65
#define KT_STR 104
#define VS_STR 68
#define SC_STR 104
#define ATT_FLOATS (S_ * QS_STR + DEPTH_ * KT_STR + S_ * VS_STR + S_ * SC_STR)
#define ATT_SMEM (ATT_FLOATS * 4)

__global__ __launch_bounds__(256)
void attention_kernel(const float* __restrict__ QKV, float* __restrict__ ctx) {
    extern __shared__ float sm[];
    float* qs = sm;                        // [S_][65]
    float* kt = qs + S_ * QS_STR;          // [64][104] transposed K
    float* vs = kt + DEPTH_ * KT_STR;      // [S_][68]
    float* sc = vs + S_ * VS_STR;          // [S_][104]

    int bh = blockIdx.x;
    int b = bh / H_;
    int h = bh % H_;
    int tid = threadIdx.x;
    int lane = tid & 31, warp = tid >> 5;

    // Load q/k/v. float4 gmem loads; k stored transposed.
    for (int i = tid; i < S_ * (DEPTH_ / 4); i += 256) {
        int s = i >> 4, e4 = (i & 15) * 4;
        size_t off = ((size_t)(b * S_ + s)) * N_QKV + h * DEPTH_ + e4;
        float4 q = *(const float4*)(QKV + off);
        float4 k = *(const float4*)(QKV + off + D_);
        float4 v = *(const float4*)(QKV + off + 2 * D_);
        qs[s * QS_STR + e4 + 0] = q.x; qs[s * QS_STR + e4 + 1] = q.y;
        qs[s * QS_STR + e4 + 2] = q.z; qs[s * QS_STR + e4 + 3] = q.w;
        kt[(e4 + 0) * KT_STR + s] = k.x; kt[(e4 + 1) * KT_STR + s] = k.y;
        kt[(e4 + 2) * KT_STR + s] = k.z; kt[(e4 + 3) * KT_STR + s] = k.w;
        *(float4*)&vs[s * VS_STR + e4] = v;
    }
    __syncthreads();

    // QK^T: 4x4 register tiles. 25x25 = 625 tiles.
    const float scale = 0.125f;
    for (int t = tid; t < 625; t += 256) {
        int i0 = (t / 25) * 4, j0 = (t % 25) * 4;
        float a[4][4];
#pragma unroll
        for (int u = 0; u < 4; u++)
#pragma unroll
            for (int v = 0; v < 4; v++) a[u][v] = 0.f;
#pragma unroll 8
        for (int e = 0; e < DEPTH_; e++) {
            float4 kv = *(const float4*)&kt[e * KT_STR + j0];
            float q0 = qs[(i0 + 0) * QS_STR + e];
            float q1 = qs[(i0 + 1) * QS_STR + e];
            float q2 = qs[(i0 + 2) * QS_STR + e];
            float q3 = qs[(i0 + 3) * QS_STR + e];
            a[0][0] += q0 * kv.x; a[0][1] += q0 * kv.y; a[0][2] += q0 * kv.z; a[0][3] += q0 * kv.w;
            a[1][0] += q1 * kv.x; a[1][1] += q1 * kv.y; a[1][2] += q1 * kv.z; a[1][3] += q1 * kv.w;
            a[2][0] += q2 * kv.x; a[2][1] += q2 * kv.y; a[2][2] += q2 * kv.z; a[2][3] += q2 * kv.w;
            a[3][0] += q3 * kv.x; a[3][1] += q3 * kv.y; a[3][2] += q3 * kv.z; a[3][3] += q3 * kv.w;
        }
#pragma unroll
        for (int u = 0; u < 4; u++) {
            float4 o = make_float4(a[u][0] * scale, a[u][1] * scale,
                                   a[u][2] * scale, a[u][3] * scale);
            *(float4*)&sc[(i0 + u) * SC_STR + j0] = o;
        }
    }
    __syncthreads();

    // Softmax: warp per row (8 warps cover 100 rows in 13 rounds).
    for (int r = warp; r < S_; r += 8) {
        float v0 = (lane < S_) ? sc[r * SC_STR + lane] : -1e30f;
        float v1 = sc[r * SC_STR + lane + 32];          // 32..63 < 100
        float v2 = (lane + 64 < S_) ? sc[r * SC_STR + lane + 64] : -1e30f;
        float v3 = (lane + 96 < S_) ? sc[r * SC_STR + lane + 96] : -1e30f;
        float m = fmaxf(fmaxf(v0, v1), fmaxf(v2, v3));
#pragma unroll
        for (int off = 16; off > 0; off >>= 1)
            m = fmaxf(m, __shfl_xor_sync(0xffffffffu, m, off));
        float e0 = (lane < S_) ? __expf(v0 - m) : 0.f;
        float e1 = __expf(v1 - m);
        float e2 = (lane + 64 < S_) ? __expf(v2 - m) : 0.f;
        float e3 = (lane + 96 < S_) ? __expf(v3 - m) : 0.f;
        float s = e0 + e1 + e2 + e3;
#pragma unroll
        for (int off = 16; off > 0; off >>= 1)
            s += __shfl_xor_sync(0xffffffffu, s, off);
        float inv = 1.f / s;
        if (lane < S_) sc[r * SC_STR + lane] = e0 * inv;
        sc[r * SC_STR + lane + 32] = e1 * inv;
        if (lane + 64 < S_) sc[r * SC_STR + lane + 64] = e2 * inv;
        if (lane + 96 < S_) sc[r * SC_STR + lane + 96] = e3 * inv;
    }
    __syncthreads();

    // AV: thread computes (i, e4): 100*16 = 1600 work items.
    const size_t cbase = (size_t)b * S_ * D_ + (size_t)h * DEPTH_;
    for (int t = tid; t < S_ * 16; t += 256) {
        int i = t >> 4, e4 = (t & 15) * 4;
        float a0 = 0.f, a1 = 0.f, a2 = 0.f, a3 = 0.f;
        const float* srow = sc + i * SC_STR;
#pragma unroll 4
        for (int j = 0; j < S_; j++) {
            float w = srow[j];
            float4 v = *(const float4*)&vs[j * VS_STR + e4];
            a0 += w * v.x; a1 += w * v.y; a2 += w * v.z; a3 += w * v.w;
        }
        float4 o = make_float4(roundtf(a0), roundtf(a1), roundtf(a2), roundtf(a3));
        *(float4*)&ctx[cbase + (size_t)i * D_ + e4] = o;
    }
}

// ---------------------------------------------------------------------------
// LayerNorm; optionally also writes tf32-rounded twin.
// ---------------------------------------------------------------------------
template <bool ROUND2>
__global__ __launch_bounds__(256)
void layernorm_kernel(const float* __restrict__ in, const float* __restrict__ gamma,
                      const float* __restrict__ beta, float* __restrict__ out,
                      float* __restrict__ out_r) {
    int row = blockIdx.x;
    const float* p = in + (size_t)row * D_;
    int tid = threadIdx.x;

    float vals[4];
    float sum = 0.f, sq = 0.f;
#pragma unroll
    for (int r = 0; r < 4; r++) {
        float v = p[tid + r * 256];
        vals[r] = v;
        sum += v;
        sq += v * v;
    }
#pragma unroll
    for (int off = 16; off > 0; off >>= 1) {
        sum += __shfl_xor_sync(0xffffffffu, sum, off);
        sq += __shfl_xor_sync(0xffffffffu, sq, off);
    }
    __shared__ float s1[8], s2[8];
    int wid = tid >> 5, lid = tid & 31;
    if (lid == 0) { s1[wid] = sum; s2[wid] = sq; }
    __syncthreads();
    if (wid == 0) {
        sum = (lid < 8) ? s1[lid] : 0.f;
        sq = (lid < 8) ? s2[lid] : 0.f;
#pragma unroll
        for (int off = 4; off > 0; off >>= 1) {
            sum += __shfl_xor_sync(0xffffffffu, sum, off);
            sq += __shfl_xor_sync(0xffffffffu, sq, off);
        }
        if (lid == 0) { s1[0] = sum; s2[0] = sq; }
    }
    __syncthreads();
    float mean = s1[0] * (1.0f / D_);
    float var = s2[0] * (1.0f / D_) - mean * mean;
    float inv = rsqrtf(var + EPS_);
#pragma unroll
    for (int r = 0; r < 4; r++) {
        int d = tid + r * 256;
        float o = gamma[d] * ((vals[r] - mean) * inv) + beta[d];
        out[(size_t)row * D_ + d] = o;
        if (ROUND2) out_r[(size_t)row * D_ + d] = roundtf(o);
    }
}

// ---------------------------------------------------------------------------
// Launch
// ---------------------------------------------------------------------------
extern "C" void kernel_launch(void* const* d_in, const int* in_sizes, int n_in,
                              void* d_out, int out_size) {
    const int* tokens = (const int*)d_in[0];
    const float* emb = (const float*)d_in[1];
    const float* Wq = (const float*)d_in[2];
    const float* bq = (const float*)d_in[3];
    const float* Wk = (const float*)d_in[4];
    const float* bk = (const float*)d_in[5];
    const float* Wv = (const float*)d_in[6];
    const float* bv = (const float*)d_in[7];
    const float* Wo = (const float*)d_in[8];
    const float* bo = (const float*)d_in[9];
    const float* W1 = (const float*)d_in[10];
    const float* b1 = (const float*)d_in[11];
    const float* W2 = (const float*)d_in[12];
    const float* b2 = (const float*)d_in[13];
    const float* gamma1 = (const float*)d_in[14];
    const float* beta1 = (const float*)d_in[15];
    const float* gamma2 = (const float*)d_in[16];
    const float* beta2 = (const float*)d_in[17];
    float* out = (float*)d_out;

    float *pe, *x, *xr, *Wqkv, *bqkv, *Wor, *W1r, *W2r, *QKV, *ctx, *t1, *x1, *x1r, *ffh;
    cudaGetSymbolAddress((void**)&pe, g_pe);
    cudaGetSymbolAddress((void**)&x, g_x);
    cudaGetSymbolAddress((void**)&xr, g_xr);
    cudaGetSymbolAddress((void**)&Wqkv, g_Wqkv);
    cudaGetSymbolAddress((void**)&bqkv, g_bqkv);
    cudaGetSymbolAddress((void**)&Wor, g_Wor);
    cudaGetSymbolAddress((void**)&W1r, g_W1r);
    cudaGetSymbolAddress((void**)&W2r, g_W2r);
    cudaGetSymbolAddress((void**)&QKV, g_QKV);
    cudaGetSymbolAddress((void**)&ctx, g_ctx);
    cudaGetSymbolAddress((void**)&t1, g_t1);
    cudaGetSymbolAddress((void**)&x1, g_x1);
    cudaGetSymbolAddress((void**)&x1r, g_x1r);
    cudaGetSymbolAddress((void**)&ffh, g_ffh);

    cudaFuncSetAttribute(attention_kernel,
                         cudaFuncAttributeMaxDynamicSharedMemorySize, ATT_SMEM);
    cudaFuncSetAttribute(mma_gemm<1>,
                         cudaFuncAttributeMaxDynamicSharedMemorySize, SMEM_GEMM);
    cudaFuncSetAttribute(mma_gemm<5>,
                         cudaFuncAttributeMaxDynamicSharedMemorySize, SMEM_GEMM);
    cudaFuncSetAttribute(mma_gemm<11>,
                         cudaFuncAttributeMaxDynamicSharedMemorySize, SMEM_GEMM);

    // 1. positional encoding + embedding (+ rounded twin)
    pe_kernel<<<(S_ * D_ + 255) / 256, 256>>>(pe);
    embed_kernel<<<(BS_ * D_ / 4 + 255) / 256, 256>>>(tokens, emb, pe, x, xr);

    // 2. weight prep: QKV permute (rounded) + round-copies of Wo/W1/W2
    permute_qkv_kernel<<<(3 * D_ * D_ + 255) / 256, 256>>>(Wq, Wk, Wv, bq, bk, bv,
                                                           Wqkv, bqkv);
    roundcpy_kernel<<<(D_ * D_ / 4 + 255) / 256, 256>>>(Wo, Wor, D_ * D_ / 4);
    roundcpy_kernel<<<(D_ * F_ / 4 + 255) / 256, 256>>>(W1, W1r, D_ * F_ / 4);
    roundcpy_kernel<<<(F_ * D_ / 4 + 255) / 256, 256>>>(W2, W2r, F_ * D_ / 4);

    // 3. fused QKV projection
    mma_gemm<1><<<dim3(N_QKV / 128, BS_ / 128), 256, SMEM_GEMM>>>(
        xr, Wqkv, QKV, bqkv, nullptr, BS_, N_QKV, D_);

    // 4. attention (rounds ctx)
    attention_kernel<<<B_ * H_, 256, ATT_SMEM>>>(QKV, ctx);

    // 5. output projection + residual (fp32 x), LN1 (+rounded twin)
    mma_gemm<5><<<dim3(D_ / 128, BS_ / 128), 256, SMEM_GEMM>>>(
        ctx, Wor, t1, bo, x, BS_, D_, D_);
    layernorm_kernel<true><<<BS_, 256>>>(t1, gamma1, beta1, x1, x1r);

    // 6. FFN
    mma_gemm<11><<<dim3(F_ / 128, BS_ / 128), 256, SMEM_GEMM>>>(
        x1r, W1r, ffh, b1, nullptr, BS_, F_, D_);
    mma_gemm<5><<<dim3(D_ / 128, BS_ / 128), 256, SMEM_GEMM>>>(
        ffh, W2r, t1, b2, x1, BS_, D_, F_);

    // 7. LN2 -> output
    layernorm_kernel<false><<<BS_, 256>>>(t1, gamma2, beta2, out, nullptr);
}

// round 5
// speedup vs baseline: 3.9646x; 1.0156x over previous
#include <cuda_runtime.h>
#include <cuda_bf16.h>
#include <math.h>
#include <stdint.h>

// Problem constants
#define B_ 64
#define S_ 100
#define D_ 1024
#define H_ 16
#define F_ 4096
#define DEPTH_ 64
#define BS_ (B_ * S_)          // 6400
#define N_QKV 3072
#define EPS_ 1e-6f

// ---------------------------------------------------------------------------
// Scratch (device globals; no allocations allowed)
// ---------------------------------------------------------------------------
__device__ float g_pe[S_ * D_];
__device__ float g_x[BS_ * D_];      // full fp32 (residual path)
__device__ float g_xr[BS_ * D_];     // tf32-rounded (GEMM A operand)
__device__ float g_Wqkv[D_ * N_QKV]; // rounded, [K,N]
__device__ float g_bqkv[N_QKV];
__device__ float g_Wor[D_ * D_];     // rounded Wo [K,N]
__device__ float g_W1r[D_ * F_];     // rounded W1 [K,N]
__device__ float g_W2r[F_ * D_];     // rounded W2 [K,N]
__device__ float g_QKV[BS_ * N_QKV];
__device__ float g_ctx[BS_ * D_];    // rounded at attention epilogue
__device__ float g_t1[BS_ * D_];
__device__ float g_x1[BS_ * D_];
__device__ float g_x1r[BS_ * D_];
__device__ float g_ffh[BS_ * F_];    // rounded at relu epilogue

__device__ __forceinline__ uint32_t f2tf32(float x) {
    uint32_t r;
    asm("cvt.rna.tf32.f32 %0, %1;" : "=r"(r) : "f"(x));
    return r;
}
__device__ __forceinline__ float roundtf(float x) {
    return __uint_as_float(f2tf32(x));
}

// ---------------------------------------------------------------------------
// Positional encoding (fp64 to match numpy float64 table)
// ---------------------------------------------------------------------------
__global__ void pe_kernel(float* __restrict__ pe) {
    int idx = blockIdx.x * blockDim.x + threadIdx.x;
    if (idx >= S_ * D_) return;
    int s = idx / D_;
    int d = idx % D_;
    int k2 = d & ~1;
    double div = pow(10000.0, (double)k2 / (double)D_);
    double arg = (double)s / div;
    pe[idx] = (float)((d & 1) ? cos(arg) : sin(arg));
}

// ---------------------------------------------------------------------------
// Embedding gather + positional add; writes fp32 x and tf32-rounded xr
// ---------------------------------------------------------------------------
__global__ void embed_kernel(const int* __restrict__ tokens,
                             const float* __restrict__ emb,
                             const float* __restrict__ pe,
                             float* __restrict__ x, float* __restrict__ xr) {
    int idx = blockIdx.x * blockDim.x + threadIdx.x;
    if (idx >= BS_ * D_ / 4) return;
    int row = idx / (D_ / 4);
    int c4 = idx % (D_ / 4);
    int tok = tokens[row];
    float4 e = ((const float4*)(emb + (size_t)tok * D_))[c4];
    float4 p = ((const float4*)(pe + (size_t)(row % S_) * D_))[c4];
    float4 o;
    o.x = e.x + p.x; o.y = e.y + p.y; o.z = e.z + p.z; o.w = e.w + p.w;
    ((float4*)x)[idx] = o;
    float4 r;
    r.x = roundtf(o.x); r.y = roundtf(o.y); r.z = roundtf(o.z); r.w = roundtf(o.w);
    ((float4*)xr)[idx] = r;
}

// ---------------------------------------------------------------------------
// Permute Wq/Wk/Wv [H,D,64] -> combined [D, 3072] (rounded); biases -> [3072]
// ---------------------------------------------------------------------------
__global__ void permute_qkv_kernel(const float* __restrict__ Wq, const float* __restrict__ Wk,
                                   const float* __restrict__ Wv,
                                   const float* __restrict__ bq, const float* __restrict__ bk,
                                   const float* __restrict__ bv,
                                   float* __restrict__ Wout, float* __restrict__ bout) {
    int idx = blockIdx.x * blockDim.x + threadIdx.x;
    const int total = 3 * D_ * D_;
    if (idx < total) {
        int which = idx / (D_ * D_);
        int r = idx % (D_ * D_);
        int d = r / D_;
        int n = r % D_;
        int h = n >> 6, e = n & 63;
        const float* W = (which == 0) ? Wq : ((which == 1) ? Wk : Wv);
        Wout[(size_t)d * N_QKV + which * D_ + n] =
            roundtf(W[((size_t)h * D_ + d) * DEPTH_ + e]);
    }
    if (idx < N_QKV) {
        int which = idx / D_;
        int n = idx % D_;
        const float* bb = (which == 0) ? bq : ((which == 1) ? bk : bv);
        bout[idx] = bb[n];
    }
}

// ---------------------------------------------------------------------------
// tf32 round-copy
// ---------------------------------------------------------------------------
__global__ void roundcpy_kernel(const float* __restrict__ in, float* __restrict__ out, int n4) {
    int idx = blockIdx.x * blockDim.x + threadIdx.x;
    if (idx >= n4) return;
    float4 v = ((const float4*)in)[idx];
    float4 r;
    r.x = roundtf(v.x); r.y = roundtf(v.y); r.z = roundtf(v.z); r.w = roundtf(v.w);
    ((float4*)out)[idx] = r;
}

// ---------------------------------------------------------------------------
// TF32 mma.sync GEMM (pre-rounded inputs; no cvt in mainloop).
// 128x128 CTA tile, 4 warps of 64x64, k-step 32, cp.async double buffer.
// EPI: bit0 bias, bit1 relu, bit2 residual, bit3 round-output.
// ---------------------------------------------------------------------------
#define ASTRIDE 44
#define BSTRIDE 136
#define AFLOATS (128 * ASTRIDE)
#define BFLOATS (32 * BSTRIDE)
#define STAGEF  (AFLOATS + BFLOATS)
#define SMEM_GEMM (2 * STAGEF * 4)

__device__ __forceinline__ void mma_tf32(float* d, const uint32_t* a, const uint32_t* b) {
    asm volatile(
        "mma.sync.aligned.m16n8k8.row.col.f32.tf32.tf32.f32 "
        "{%0,%1,%2,%3}, {%4,%5,%6,%7}, {%8,%9}, {%0,%1,%2,%3};\n"
        : "+f"(d[0]), "+f"(d[1]), "+f"(d[2]), "+f"(d[3])
        : "r"(a[0]), "r"(a[1]), "r"(a[2]), "r"(a[3]), "r"(b[0]), "r"(b[1]));
}

template <int EPI>
__global__ __launch_bounds__(128, 2)
void mma_gemm(const float* __restrict__ A, const float* __restrict__ Bm,
              float* __restrict__ C, const float* __restrict__ bias,
              const float* __restrict__ res, int M, int N, int K) {
    extern __shared__ float smf[];
    int tid = threadIdx.x;
    int lane = tid & 31, warp = tid >> 5;
    int wm = warp & 1, wn = warp >> 1;     // 2x2 warp grid, 64x64 tiles
    int g = lane >> 2, tg = lane & 3;
    int bm = blockIdx.y * 128, bn = blockIdx.x * 128;

    uint32_t smemBase = (uint32_t)__cvta_generic_to_shared(smf);

    float acc[4][8][4];
#pragma unroll
    for (int i = 0; i < 4; i++)
#pragma unroll
        for (int j = 0; j < 8; j++)
#pragma unroll
            for (int c = 0; c < 4; c++) acc[i][j][c] = 0.f;

    const int KT = K / 32;

    // Prefetch geometry (128 threads):
    // A tile 128x32: chunk c = q*128+tid, row=c>>3 (tid>>3 + q*16), col=c&7
    // B tile 32x128: chunk c = q*128+tid, krow=c>>5 (tid>>5 + q*4), col=c&31
    int aRow = tid >> 3, aColv = tid & 7;
    int bKrow = tid >> 5, bColv = tid & 31;
    const float* aSrc = A + (size_t)(bm + aRow) * K + aColv * 4;
    const float* bSrc = Bm + (size_t)bKrow * N + bn + bColv * 4;
    uint32_t aDst0 = smemBase + (uint32_t)(aRow * ASTRIDE + aColv * 4) * 4;
    uint32_t bDst0 = smemBase + AFLOATS * 4 + (uint32_t)(bKrow * BSTRIDE + bColv * 4) * 4;

    auto prefetch = [&](int stage) {
        uint32_t so = (uint32_t)(stage * STAGEF * 4);
#pragma unroll
        for (int q = 0; q < 8; q++) {
            uint32_t dst = aDst0 + so + (uint32_t)(q * 16 * ASTRIDE) * 4;
            const float* src = aSrc + (size_t)(q * 16) * K;
            asm volatile("cp.async.cg.shared.global [%0], [%1], 16;" :: "r"(dst), "l"(src));
        }
#pragma unroll
        for (int q = 0; q < 8; q++) {
            uint32_t dst = bDst0 + so + (uint32_t)(q * 4 * BSTRIDE) * 4;
            const float* src = bSrc + (size_t)(q * 4) * N;
            asm volatile("cp.async.cg.shared.global [%0], [%1], 16;" :: "r"(dst), "l"(src));
        }
        aSrc += 32;
        bSrc += (size_t)32 * N;
    };

    prefetch(0);
    asm volatile("cp.async.commit_group;");

    for (int kt = 0; kt < KT; kt++) {
        if (kt + 1 < KT) prefetch((kt + 1) & 1);
        asm volatile("cp.async.commit_group;");
        asm volatile("cp.async.wait_group 1;");
        __syncthreads();

        const uint32_t* As = (const uint32_t*)(smf + (kt & 1) * STAGEF);
        const uint32_t* Bs = As + AFLOATS;
#pragma unroll
        for (int ks = 0; ks < 4; ks++) {
            int k0 = ks * 8;
            uint32_t afr[4][4];
#pragma unroll
            for (int mi = 0; mi < 4; mi++) {
                int m = wm * 64 + mi * 16 + g;
                afr[mi][0] = As[m * ASTRIDE + k0 + tg];
                afr[mi][1] = As[(m + 8) * ASTRIDE + k0 + tg];
                afr[mi][2] = As[m * ASTRIDE + k0 + tg + 4];
                afr[mi][3] = As[(m + 8) * ASTRIDE + k0 + tg + 4];
            }
            uint32_t bfr[8][2];
#pragma unroll
            for (int ni = 0; ni < 8; ni++) {
                int n = wn * 64 + ni * 8 + g;
                bfr[ni][0] = Bs[(k0 + tg) * BSTRIDE + n];
                bfr[ni][1] = Bs[(k0 + tg + 4) * BSTRIDE + n];
            }
#pragma unroll
            for (int mi = 0; mi < 4; mi++)
#pragma unroll
                for (int ni = 0; ni < 8; ni++)
                    mma_tf32(acc[mi][ni], afr[mi], bfr[ni]);
        }
        __syncthreads();
    }

#pragma unroll
    for (int mi = 0; mi < 4; mi++) {
#pragma unroll
        for (int rr = 0; rr < 2; rr++) {
            int row = bm + wm * 64 + mi * 16 + rr * 8 + g;
#pragma unroll
            for (int ni = 0; ni < 8; ni++) {
                int col = bn + wn * 64 + ni * 8 + tg * 2;
                float vx = acc[mi][ni][rr * 2 + 0];
                float vy = acc[mi][ni][rr * 2 + 1];
                if (EPI & 1) { vx += bias[col]; vy += bias[col + 1]; }
                if (EPI & 4) {
                    const float* rp = res + (size_t)row * N + col;
                    vx += rp[0]; vy += rp[1];
                }
                if (EPI & 2) { vx = fmaxf(vx, 0.f); vy = fmaxf(vy, 0.f); }
                if (EPI & 8) { vx = roundtf(vx); vy = roundtf(vy); }
                *(float2*)&C[(size_t)row * N + col] = make_float2(vx, vy);
            }
        }
    }
}

// ---------------------------------------------------------------------------
// Fused attention per (b, h). Register-tiled QK (4x4), transposed K in smem,
// warp-parallel softmax, float4 AV. Output rounded to tf32.
// ---------------------------------------------------------------------------
#define QS_STR 65
#define KT_STR 104
#define VS_STR 68
#define SC_STR 104
#define ATT_FLOATS (S_ * QS_STR + DEPTH_ * KT_STR + S_ * VS_STR + S_ * SC_STR)
#define ATT_SMEM (ATT_FLOATS * 4)

__global__ __launch_bounds__(256)
void attention_kernel(const float* __restrict__ QKV, float* __restrict__ ctx) {
    extern __shared__ float sm[];
    float* qs = sm;
    float* kt = qs + S_ * QS_STR;
    float* vs = kt + DEPTH_ * KT_STR;
    float* sc = vs + S_ * VS_STR;

    int bh = blockIdx.x;
    int b = bh / H_;
    int h = bh % H_;
    int tid = threadIdx.x;
    int lane = tid & 31, warp = tid >> 5;

    for (int i = tid; i < S_ * (DEPTH_ / 4); i += 256) {
        int s = i >> 4, e4 = (i & 15) * 4;
        size_t off = ((size_t)(b * S_ + s)) * N_QKV + h * DEPTH_ + e4;
        float4 q = *(const float4*)(QKV + off);
        float4 k = *(const float4*)(QKV + off + D_);
        float4 v = *(const float4*)(QKV + off + 2 * D_);
        qs[s * QS_STR + e4 + 0] = q.x; qs[s * QS_STR + e4 + 1] = q.y;
        qs[s * QS_STR + e4 + 2] = q.z; qs[s * QS_STR + e4 + 3] = q.w;
        kt[(e4 + 0) * KT_STR + s] = k.x; kt[(e4 + 1) * KT_STR + s] = k.y;
        kt[(e4 + 2) * KT_STR + s] = k.z; kt[(e4 + 3) * KT_STR + s] = k.w;
        *(float4*)&vs[s * VS_STR + e4] = v;
    }
    __syncthreads();

    const float scale = 0.125f;
    for (int t = tid; t < 625; t += 256) {
        int i0 = (t / 25) * 4, j0 = (t % 25) * 4;
        float a[4][4];
#pragma unroll
        for (int u = 0; u < 4; u++)
#pragma unroll
            for (int v = 0; v < 4; v++) a[u][v] = 0.f;
#pragma unroll 8
        for (int e = 0; e < DEPTH_; e++) {
            float4 kv = *(const float4*)&kt[e * KT_STR + j0];
            float q0 = qs[(i0 + 0) * QS_STR + e];
            float q1 = qs[(i0 + 1) * QS_STR + e];
            float q2 = qs[(i0 + 2) * QS_STR + e];
            float q3 = qs[(i0 + 3) * QS_STR + e];
            a[0][0] += q0 * kv.x; a[0][1] += q0 * kv.y; a[0][2] += q0 * kv.z; a[0][3] += q0 * kv.w;
            a[1][0] += q1 * kv.x; a[1][1] += q1 * kv.y; a[1][2] += q1 * kv.z; a[1][3] += q1 * kv.w;
            a[2][0] += q2 * kv.x; a[2][1] += q2 * kv.y; a[2][2] += q2 * kv.z; a[2][3] += q2 * kv.w;
            a[3][0] += q3 * kv.x; a[3][1] += q3 * kv.y; a[3][2] += q3 * kv.z; a[3][3] += q3 * kv.w;
        }
#pragma unroll
        for (int u = 0; u < 4; u++) {
            float4 o = make_float4(a[u][0] * scale, a[u][1] * scale,
                                   a[u][2] * scale, a[u][3] * scale);
            *(float4*)&sc[(i0 + u) * SC_STR + j0] = o;
        }
    }
    __syncthreads();

    for (int r = warp; r < S_; r += 8) {
        float v0 = (lane < S_) ? sc[r * SC_STR + lane] : -1e30f;
        float v1 = sc[r * SC_STR + lane + 32];
        float v2 = (lane + 64 < S_) ? sc[r * SC_STR + lane + 64] : -1e30f;
        float v3 = (lane + 96 < S_) ? sc[r * SC_STR + lane + 96] : -1e30f;
        float m = fmaxf(fmaxf(v0, v1), fmaxf(v2, v3));
#pragma unroll
        for (int off = 16; off > 0; off >>= 1)
            m = fmaxf(m, __shfl_xor_sync(0xffffffffu, m, off));
        float e0 = (lane < S_) ? __expf(v0 - m) : 0.f;
        float e1 = __expf(v1 - m);
        float e2 = (lane + 64 < S_) ? __expf(v2 - m) : 0.f;
        float e3 = (lane + 96 < S_) ? __expf(v3 - m) : 0.f;
        float s = e0 + e1 + e2 + e3;
#pragma unroll
        for (int off = 16; off > 0; off >>= 1)
            s += __shfl_xor_sync(0xffffffffu, s, off);
        float inv = 1.f / s;
        if (lane < S_) sc[r * SC_STR + lane] = e0 * inv;
        sc[r * SC_STR + lane + 32] = e1 * inv;
        if (lane + 64 < S_) sc[r * SC_STR + lane + 64] = e2 * inv;
        if (lane + 96 < S_) sc[r * SC_STR + lane + 96] = e3 * inv;
    }
    __syncthreads();

    const size_t cbase = (size_t)b * S_ * D_ + (size_t)h * DEPTH_;
    for (int t = tid; t < S_ * 16; t += 256) {
        int i = t >> 4, e4 = (t & 15) * 4;
        float a0 = 0.f, a1 = 0.f, a2 = 0.f, a3 = 0.f;
        const float* srow = sc + i * SC_STR;
#pragma unroll 4
        for (int j = 0; j < S_; j++) {
            float w = srow[j];
            float4 v = *(const float4*)&vs[j * VS_STR + e4];
            a0 += w * v.x; a1 += w * v.y; a2 += w * v.z; a3 += w * v.w;
        }
        float4 o = make_float4(roundtf(a0), roundtf(a1), roundtf(a2), roundtf(a3));
        *(float4*)&ctx[cbase + (size_t)i * D_ + e4] = o;
    }
}

// ---------------------------------------------------------------------------
// LayerNorm; optional tf32-rounded twin.
// ---------------------------------------------------------------------------
template <bool ROUND2>
__global__ __launch_bounds__(256)
void layernorm_kernel(const float* __restrict__ in, const float* __restrict__ gamma,
                      const float* __restrict__ beta, float* __restrict__ out,
                      float* __restrict__ out_r) {
    int row = blockIdx.x;
    const float* p = in + (size_t)row * D_;
    int tid = threadIdx.x;

    float vals[4];
    float sum = 0.f, sq = 0.f;
#pragma unroll
    for (int r = 0; r < 4; r++) {
        float v = p[tid + r * 256];
        vals[r] = v;
        sum += v;
        sq += v * v;
    }
#pragma unroll
    for (int off = 16; off > 0; off >>= 1) {
        sum += __shfl_xor_sync(0xffffffffu, sum, off);
        sq += __shfl_xor_sync(0xffffffffu, sq, off);
    }
    __shared__ float s1[8], s2[8];
    int wid = tid >> 5, lid = tid & 31;
    if (lid == 0) { s1[wid] = sum; s2[wid] = sq; }
    __syncthreads();
    if (wid == 0) {
        sum = (lid < 8) ? s1[lid] : 0.f;
        sq = (lid < 8) ? s2[lid] : 0.f;
#pragma unroll
        for (int off = 4; off > 0; off >>= 1) {
            sum += __shfl_xor_sync(0xffffffffu, sum, off);
            sq += __shfl_xor_sync(0xffffffffu, sq, off);
        }
        if (lid == 0) { s1[0] = sum; s2[0] = sq; }
    }
    __syncthreads();
    float mean = s1[0] * (1.0f / D_);
    float var = s2[0] * (1.0f / D_) - mean * mean;
    float inv = rsqrtf(var + EPS_);
#pragma unroll
    for (int r = 0; r < 4; r++) {
        int d = tid + r * 256;
        float o = gamma[d] * ((vals[r] - mean) * inv) + beta[d];
        out[(size_t)row * D_ + d] = o;
        if (ROUND2) out_r[(size_t)row * D_ + d] = roundtf(o);
    }
}

// ---------------------------------------------------------------------------
// Launch
// ---------------------------------------------------------------------------
extern "C" void kernel_launch(void* const* d_in, const int* in_sizes, int n_in,
                              void* d_out, int out_size) {
    const int* tokens = (const int*)d_in[0];
    const float* emb = (const float*)d_in[1];
    const float* Wq = (const float*)d_in[2];
    const float* bq = (const float*)d_in[3];
    const float* Wk = (const float*)d_in[4];
    const float* bk = (const float*)d_in[5];
    const float* Wv = (const float*)d_in[6];
    const float* bv = (const float*)d_in[7];
    const float* Wo = (const float*)d_in[8];
    const float* bo = (const float*)d_in[9];
    const float* W1 = (const float*)d_in[10];
    const float* b1 = (const float*)d_in[11];
    const float* W2 = (const float*)d_in[12];
    const float* b2 = (const float*)d_in[13];
    const float* gamma1 = (const float*)d_in[14];
    const float* beta1 = (const float*)d_in[15];
    const float* gamma2 = (const float*)d_in[16];
    const float* beta2 = (const float*)d_in[17];
    float* out = (float*)d_out;

    float *pe, *x, *xr, *Wqkv, *bqkv, *Wor, *W1r, *W2r, *QKV, *ctx, *t1, *x1, *x1r, *ffh;
    cudaGetSymbolAddress((void**)&pe, g_pe);
    cudaGetSymbolAddress((void**)&x, g_x);
    cudaGetSymbolAddress((void**)&xr, g_xr);
    cudaGetSymbolAddress((void**)&Wqkv, g_Wqkv);
    cudaGetSymbolAddress((void**)&bqkv, g_bqkv);
    cudaGetSymbolAddress((void**)&Wor, g_Wor);
    cudaGetSymbolAddress((void**)&W1r, g_W1r);
    cudaGetSymbolAddress((void**)&W2r, g_W2r);
    cudaGetSymbolAddress((void**)&QKV, g_QKV);
    cudaGetSymbolAddress((void**)&ctx, g_ctx);
    cudaGetSymbolAddress((void**)&t1, g_t1);
    cudaGetSymbolAddress((void**)&x1, g_x1);
    cudaGetSymbolAddress((void**)&x1r, g_x1r);
    cudaGetSymbolAddress((void**)&ffh, g_ffh);

    cudaFuncSetAttribute(attention_kernel,
                         cudaFuncAttributeMaxDynamicSharedMemorySize, ATT_SMEM);
    cudaFuncSetAttribute(mma_gemm<1>,
                         cudaFuncAttributeMaxDynamicSharedMemorySize, SMEM_GEMM);
    cudaFuncSetAttribute(mma_gemm<5>,
                         cudaFuncAttributeMaxDynamicSharedMemorySize, SMEM_GEMM);
    cudaFuncSetAttribute(mma_gemm<11>,
                         cudaFuncAttributeMaxDynamicSharedMemorySize, SMEM_GEMM);

    // 1. positional encoding + embedding (+ rounded twin)
    pe_kernel<<<(S_ * D_ + 255) / 256, 256>>>(pe);
    embed_kernel<<<(BS_ * D_ / 4 + 255) / 256, 256>>>(tokens, emb, pe, x, xr);

    // 2. weight prep
    permute_qkv_kernel<<<(3 * D_ * D_ + 255) / 256, 256>>>(Wq, Wk, Wv, bq, bk, bv,
                                                           Wqkv, bqkv);
    roundcpy_kernel<<<(D_ * D_ / 4 + 255) / 256, 256>>>(Wo, Wor, D_ * D_ / 4);
    roundcpy_kernel<<<(D_ * F_ / 4 + 255) / 256, 256>>>(W1, W1r, D_ * F_ / 4);
    roundcpy_kernel<<<(F_ * D_ / 4 + 255) / 256, 256>>>(W2, W2r, F_ * D_ / 4);

    // 3. fused QKV projection
    mma_gemm<1><<<dim3(N_QKV / 128, BS_ / 128), 128, SMEM_GEMM>>>(
        xr, Wqkv, QKV, bqkv, nullptr, BS_, N_QKV, D_);

    // 4. attention (rounds ctx)
    attention_kernel<<<B_ * H_, 256, ATT_SMEM>>>(QKV, ctx);

    // 5. output projection + residual, LN1 (+rounded twin)
    mma_gemm<5><<<dim3(D_ / 128, BS_ / 128), 128, SMEM_GEMM>>>(
        ctx, Wor, t1, bo, x, BS_, D_, D_);
    layernorm_kernel<true><<<BS_, 256>>>(t1, gamma1, beta1, x1, x1r);

    // 6. FFN
    mma_gemm<11><<<dim3(F_ / 128, BS_ / 128), 128, SMEM_GEMM>>>(
        x1r, W1r, ffh, b1, nullptr, BS_, F_, D_);
    mma_gemm<5><<<dim3(D_ / 128, BS_ / 128), 128, SMEM_GEMM>>>(
        ffh, W2r, t1, b2, x1, BS_, D_, F_);

    // 7. LN2 -> output
    layernorm_kernel<false><<<BS_, 256>>>(t1, gamma2, beta2, out, nullptr);
}

// round 6
// speedup vs baseline: 4.2891x; 1.0818x over previous
#include <cuda_runtime.h>
#include <cuda_bf16.h>
#include <math.h>
#include <stdint.h>

// Problem constants
#define B_ 64
#define S_ 100
#define D_ 1024
#define H_ 16
#define F_ 4096
#define DEPTH_ 64
#define BS_ (B_ * S_)          // 6400
#define N_QKV 3072
#define EPS_ 1e-6f

// ---------------------------------------------------------------------------
// Scratch (device globals; no allocations allowed)
// ---------------------------------------------------------------------------
__device__ float g_pe[S_ * D_];
__device__ float g_x[BS_ * D_];      // full fp32 (residual path)
__device__ float g_xr[BS_ * D_];     // tf32-rounded (GEMM A operand)
__device__ float g_Wqkv[D_ * N_QKV]; // rounded, [K,N]
__device__ float g_bqkv[N_QKV];
__device__ float g_Wor[D_ * D_];     // rounded Wo [K,N]
__device__ float g_W1r[D_ * F_];     // rounded W1 [K,N]
__device__ float g_W2r[F_ * D_];     // rounded W2 [K,N]
__device__ float g_QKV[BS_ * N_QKV];
__device__ float g_ctx[BS_ * D_];    // rounded at attention epilogue
__device__ float g_t1[BS_ * D_];
__device__ float g_x1[BS_ * D_];
__device__ float g_x1r[BS_ * D_];
__device__ float g_ffh[BS_ * F_];    // rounded at relu epilogue

__device__ __forceinline__ uint32_t f2tf32(float x) {
    uint32_t r;
    asm("cvt.rna.tf32.f32 %0, %1;" : "=r"(r) : "f"(x));
    return r;
}
__device__ __forceinline__ float roundtf(float x) {
    return __uint_as_float(f2tf32(x));
}

__device__ __forceinline__ void mma_tf32(float* d, const uint32_t* a, const uint32_t* b) {
    asm volatile(
        "mma.sync.aligned.m16n8k8.row.col.f32.tf32.tf32.f32 "
        "{%0,%1,%2,%3}, {%4,%5,%6,%7}, {%8,%9}, {%0,%1,%2,%3};\n"
        : "+f"(d[0]), "+f"(d[1]), "+f"(d[2]), "+f"(d[3])
        : "r"(a[0]), "r"(a[1]), "r"(a[2]), "r"(a[3]), "r"(b[0]), "r"(b[1]));
}

// ---------------------------------------------------------------------------
// Positional encoding (fp64 to match numpy float64 table)
// ---------------------------------------------------------------------------
__global__ void pe_kernel(float* __restrict__ pe) {
    int idx = blockIdx.x * blockDim.x + threadIdx.x;
    if (idx >= S_ * D_) return;
    int s = idx / D_;
    int d = idx % D_;
    int k2 = d & ~1;
    double div = pow(10000.0, (double)k2 / (double)D_);
    double arg = (double)s / div;
    pe[idx] = (float)((d & 1) ? cos(arg) : sin(arg));
}

// ---------------------------------------------------------------------------
// Embedding gather + positional add; writes fp32 x and tf32-rounded xr
// ---------------------------------------------------------------------------
__global__ void embed_kernel(const int* __restrict__ tokens,
                             const float* __restrict__ emb,
                             const float* __restrict__ pe,
                             float* __restrict__ x, float* __restrict__ xr) {
    int idx = blockIdx.x * blockDim.x + threadIdx.x;
    if (idx >= BS_ * D_ / 4) return;
    int row = idx / (D_ / 4);
    int c4 = idx % (D_ / 4);
    int tok = tokens[row];
    float4 e = ((const float4*)(emb + (size_t)tok * D_))[c4];
    float4 p = ((const float4*)(pe + (size_t)(row % S_) * D_))[c4];
    float4 o;
    o.x = e.x + p.x; o.y = e.y + p.y; o.z = e.z + p.z; o.w = e.w + p.w;
    ((float4*)x)[idx] = o;
    float4 r;
    r.x = roundtf(o.x); r.y = roundtf(o.y); r.z = roundtf(o.z); r.w = roundtf(o.w);
    ((float4*)xr)[idx] = r;
}

// ---------------------------------------------------------------------------
// Permute Wq/Wk/Wv [H,D,64] -> combined [D, 3072] (rounded); biases -> [3072]
// ---------------------------------------------------------------------------
__global__ void permute_qkv_kernel(const float* __restrict__ Wq, const float* __restrict__ Wk,
                                   const float* __restrict__ Wv,
                                   const float* __restrict__ bq, const float* __restrict__ bk,
                                   const float* __restrict__ bv,
                                   float* __restrict__ Wout, float* __restrict__ bout) {
    int idx = blockIdx.x * blockDim.x + threadIdx.x;
    const int total = 3 * D_ * D_;
    if (idx < total) {
        int which = idx / (D_ * D_);
        int r = idx % (D_ * D_);
        int d = r / D_;
        int n = r % D_;
        int h = n >> 6, e = n & 63;
        const float* W = (which == 0) ? Wq : ((which == 1) ? Wk : Wv);
        Wout[(size_t)d * N_QKV + which * D_ + n] =
            roundtf(W[((size_t)h * D_ + d) * DEPTH_ + e]);
    }
    if (idx < N_QKV) {
        int which = idx / D_;
        int n = idx % D_;
        const float* bb = (which == 0) ? bq : ((which == 1) ? bk : bv);
        bout[idx] = bb[n];
    }
}

// ---------------------------------------------------------------------------
// Combined tf32 round-copy of Wo, W1, W2 in one launch.
// ---------------------------------------------------------------------------
#define N4_WO (D_ * D_ / 4)
#define N4_W1 (D_ * F_ / 4)
#define N4_W2 (F_ * D_ / 4)
__global__ void roundcpy3_kernel(const float* __restrict__ Wo, float* __restrict__ WoR,
                                 const float* __restrict__ W1, float* __restrict__ W1R,
                                 const float* __restrict__ W2, float* __restrict__ W2R) {
    int idx = blockIdx.x * blockDim.x + threadIdx.x;
    const float* in;
    float* out;
    int off;
    if (idx < N4_WO) { in = Wo; out = WoR; off = idx; }
    else if (idx < N4_WO + N4_W1) { in = W1; out = W1R; off = idx - N4_WO; }
    else if (idx < N4_WO + N4_W1 + N4_W2) { in = W2; out = W2R; off = idx - N4_WO - N4_W1; }
    else return;
    float4 v = ((const float4*)in)[off];
    float4 r;
    r.x = roundtf(v.x); r.y = roundtf(v.y); r.z = roundtf(v.z); r.w = roundtf(v.w);
    ((float4*)out)[off] = r;
}

// ---------------------------------------------------------------------------
// TF32 mma.sync GEMM (pre-rounded inputs). 128x128 CTA tile, 4 warps of
// 64x64, k-step 32, cp.async double buffer. (Best-known config, R5.)
// EPI: bit0 bias, bit1 relu, bit2 residual, bit3 round-output.
// ---------------------------------------------------------------------------
#define ASTRIDE 44
#define BSTRIDE 136
#define AFLOATS (128 * ASTRIDE)
#define BFLOATS (32 * BSTRIDE)
#define STAGEF  (AFLOATS + BFLOATS)
#define SMEM_GEMM (2 * STAGEF * 4)

template <int EPI>
__global__ __launch_bounds__(128, 2)
void mma_gemm(const float* __restrict__ A, const float* __restrict__ Bm,
              float* __restrict__ C, const float* __restrict__ bias,
              const float* __restrict__ res, int M, int N, int K) {
    extern __shared__ float smf[];
    int tid = threadIdx.x;
    int lane = tid & 31, warp = tid >> 5;
    int wm = warp & 1, wn = warp >> 1;
    int g = lane >> 2, tg = lane & 3;
    int bm = blockIdx.y * 128, bn = blockIdx.x * 128;

    uint32_t smemBase = (uint32_t)__cvta_generic_to_shared(smf);

    float acc[4][8][4];
#pragma unroll
    for (int i = 0; i < 4; i++)
#pragma unroll
        for (int j = 0; j < 8; j++)
#pragma unroll
            for (int c = 0; c < 4; c++) acc[i][j][c] = 0.f;

    const int KT = K / 32;

    int aRow = tid >> 3, aColv = tid & 7;
    int bKrow = tid >> 5, bColv = tid & 31;
    const float* aSrc = A + (size_t)(bm + aRow) * K + aColv * 4;
    const float* bSrc = Bm + (size_t)bKrow * N + bn + bColv * 4;
    uint32_t aDst0 = smemBase + (uint32_t)(aRow * ASTRIDE + aColv * 4) * 4;
    uint32_t bDst0 = smemBase + AFLOATS * 4 + (uint32_t)(bKrow * BSTRIDE + bColv * 4) * 4;

    auto prefetch = [&](int stage) {
        uint32_t so = (uint32_t)(stage * STAGEF * 4);
#pragma unroll
        for (int q = 0; q < 8; q++) {
            uint32_t dst = aDst0 + so + (uint32_t)(q * 16 * ASTRIDE) * 4;
            const float* src = aSrc + (size_t)(q * 16) * K;
            asm volatile("cp.async.cg.shared.global [%0], [%1], 16;" :: "r"(dst), "l"(src));
        }
#pragma unroll
        for (int q = 0; q < 8; q++) {
            uint32_t dst = bDst0 + so + (uint32_t)(q * 4 * BSTRIDE) * 4;
            const float* src = bSrc + (size_t)(q * 4) * N;
            asm volatile("cp.async.cg.shared.global [%0], [%1], 16;" :: "r"(dst), "l"(src));
        }
        aSrc += 32;
        bSrc += (size_t)32 * N;
    };

    prefetch(0);
    asm volatile("cp.async.commit_group;");

    for (int kt = 0; kt < KT; kt++) {
        if (kt + 1 < KT) prefetch((kt + 1) & 1);
        asm volatile("cp.async.commit_group;");
        asm volatile("cp.async.wait_group 1;");
        __syncthreads();

        const uint32_t* As = (const uint32_t*)(smf + (kt & 1) * STAGEF);
        const uint32_t* Bs = As + AFLOATS;
#pragma unroll
        for (int ks = 0; ks < 4; ks++) {
            int k0 = ks * 8;
            uint32_t afr[4][4];
#pragma unroll
            for (int mi = 0; mi < 4; mi++) {
                int m = wm * 64 + mi * 16 + g;
                afr[mi][0] = As[m * ASTRIDE + k0 + tg];
                afr[mi][1] = As[(m + 8) * ASTRIDE + k0 + tg];
                afr[mi][2] = As[m * ASTRIDE + k0 + tg + 4];
                afr[mi][3] = As[(m + 8) * ASTRIDE + k0 + tg + 4];
            }
            uint32_t bfr[8][2];
#pragma unroll
            for (int ni = 0; ni < 8; ni++) {
                int n = wn * 64 + ni * 8 + g;
                bfr[ni][0] = Bs[(k0 + tg) * BSTRIDE + n];
                bfr[ni][1] = Bs[(k0 + tg + 4) * BSTRIDE + n];
            }
#pragma unroll
            for (int mi = 0; mi < 4; mi++)
#pragma unroll
                for (int ni = 0; ni < 8; ni++)
                    mma_tf32(acc[mi][ni], afr[mi], bfr[ni]);
        }
        __syncthreads();
    }

#pragma unroll
    for (int mi = 0; mi < 4; mi++) {
#pragma unroll
        for (int rr = 0; rr < 2; rr++) {
            int row = bm + wm * 64 + mi * 16 + rr * 8 + g;
#pragma unroll
            for (int ni = 0; ni < 8; ni++) {
                int col = bn + wn * 64 + ni * 8 + tg * 2;
                float vx = acc[mi][ni][rr * 2 + 0];
                float vy = acc[mi][ni][rr * 2 + 1];
                if (EPI & 1) { vx += bias[col]; vy += bias[col + 1]; }
                if (EPI & 4) {
                    const float* rp = res + (size_t)row * N + col;
                    vx += rp[0]; vy += rp[1];
                }
                if (EPI & 2) { vx = fmaxf(vx, 0.f); vy = fmaxf(vy, 0.f); }
                if (EPI & 8) { vx = roundtf(vx); vy = roundtf(vy); }
                *(float2*)&C[(size_t)row * N + col] = make_float2(vx, vy);
            }
        }
    }
}

// ---------------------------------------------------------------------------
// Fused attention per (b, h) — tensor-core QK^T and AV via mma.sync tf32.
// Rows padded to 112 (7 m-tiles), score cols padded to 104 (13 n-tiles).
// Pads are zeroed; V pad rows zero so pad weights contribute nothing.
// Strides chosen conflict-free for fragment LDS:
//   QS=76, SC=108 (stride%32=12 -> banks 12g+tg distinct)
//   KT=104, VS=72 (stride%32=8  -> banks 8tg+g distinct)
// ---------------------------------------------------------------------------
#define QS_STR 76
#define KT_STR 104
#define VS_STR 72
#define SC_STR 108
#define QROWS 112
#define VROWS 104
#define SROWS 112
#define ATT_FLOATS (QROWS * QS_STR + DEPTH_ * KT_STR + VROWS * VS_STR + SROWS * SC_STR)
#define ATT_SMEM (ATT_FLOATS * 4)   // 139008 bytes

__global__ __launch_bounds__(256)
void attention_kernel(const float* __restrict__ QKV, float* __restrict__ ctx) {
    extern __shared__ float sm[];
    float* qs = sm;                           // [112][76]
    float* kt = qs + QROWS * QS_STR;          // [64][104]  K^T
    float* vs = kt + DEPTH_ * KT_STR;         // [104][72]
    float* sc = vs + VROWS * VS_STR;          // [112][108]

    int bh = blockIdx.x;
    int b = bh / H_;
    int h = bh % H_;
    int tid = threadIdx.x;
    int lane = tid & 31, warp = tid >> 5;
    int g = lane >> 2, tg = lane & 3;

    // Zero everything (covers all pad rows/cols).
    for (int i = tid; i < ATT_FLOATS; i += 256) sm[i] = 0.f;
    __syncthreads();

    // Load q/k/v (rounded to tf32 so HW truncation in MMA is identity).
    for (int i = tid; i < S_ * (DEPTH_ / 4); i += 256) {
        int s = i >> 4, e4 = (i & 15) * 4;
        size_t off = ((size_t)(b * S_ + s)) * N_QKV + h * DEPTH_ + e4;
        float4 q = *(const float4*)(QKV + off);
        float4 k = *(const float4*)(QKV + off + D_);
        float4 v = *(const float4*)(QKV + off + 2 * D_);
        qs[s * QS_STR + e4 + 0] = roundtf(q.x);
        qs[s * QS_STR + e4 + 1] = roundtf(q.y);
        qs[s * QS_STR + e4 + 2] = roundtf(q.z);
        qs[s * QS_STR + e4 + 3] = roundtf(q.w);
        kt[(e4 + 0) * KT_STR + s] = roundtf(k.x);
        kt[(e4 + 1) * KT_STR + s] = roundtf(k.y);
        kt[(e4 + 2) * KT_STR + s] = roundtf(k.z);
        kt[(e4 + 3) * KT_STR + s] = roundtf(k.w);
        float4 vr = make_float4(roundtf(v.x), roundtf(v.y), roundtf(v.z), roundtf(v.w));
        *(float4*)&vs[s * VS_STR + e4] = vr;
    }
    __syncthreads();

    // --- QK^T: warps 0..6, each one 16-row m-tile; 13 n-tiles; K=64 (8 slices).
    if (warp < 7) {
        float acc[13][4];
#pragma unroll
        for (int ni = 0; ni < 13; ni++)
#pragma unroll
            for (int c = 0; c < 4; c++) acc[ni][c] = 0.f;
        const uint32_t* qsu = (const uint32_t*)qs;
        const uint32_t* ktu = (const uint32_t*)kt;
        int m = warp * 16 + g;
#pragma unroll
        for (int ks = 0; ks < 8; ks++) {
            int k0 = ks * 8;
            uint32_t a[4];
            a[0] = qsu[m * QS_STR + k0 + tg];
            a[1] = qsu[(m + 8) * QS_STR + k0 + tg];
            a[2] = qsu[m * QS_STR + k0 + tg + 4];
            a[3] = qsu[(m + 8) * QS_STR + k0 + tg + 4];
#pragma unroll
            for (int ni = 0; ni < 13; ni++) {
                uint32_t bf[2];
                bf[0] = ktu[(k0 + tg) * KT_STR + ni * 8 + g];
                bf[1] = ktu[(k0 + tg + 4) * KT_STR + ni * 8 + g];
                mma_tf32(acc[ni], a, bf);
            }
        }
        const float scale = 0.125f;
#pragma unroll
        for (int ni = 0; ni < 13; ni++)
#pragma unroll
            for (int rr = 0; rr < 2; rr++) {
                int row = warp * 16 + rr * 8 + g;
                int col = ni * 8 + tg * 2;
                *(float2*)&sc[row * SC_STR + col] =
                    make_float2(acc[ni][rr * 2] * scale, acc[ni][rr * 2 + 1] * scale);
            }
    }
    __syncthreads();

    // --- Softmax: warp per row; weights rounded to tf32 on writeback.
    for (int r = warp; r < S_; r += 8) {
        float v0 = (lane < S_) ? sc[r * SC_STR + lane] : -1e30f;
        float v1 = sc[r * SC_STR + lane + 32];
        float v2 = (lane + 64 < S_) ? sc[r * SC_STR + lane + 64] : -1e30f;
        float v3 = (lane + 96 < S_) ? sc[r * SC_STR + lane + 96] : -1e30f;
        float m = fmaxf(fmaxf(v0, v1), fmaxf(v2, v3));
#pragma unroll
        for (int off = 16; off > 0; off >>= 1)
            m = fmaxf(m, __shfl_xor_sync(0xffffffffu, m, off));
        float e0 = (lane < S_) ? __expf(v0 - m) : 0.f;
        float e1 = __expf(v1 - m);
        float e2 = (lane + 64 < S_) ? __expf(v2 - m) : 0.f;
        float e3 = (lane + 96 < S_) ? __expf(v3 - m) : 0.f;
        float s = e0 + e1 + e2 + e3;
#pragma unroll
        for (int off = 16; off > 0; off >>= 1)
            s += __shfl_xor_sync(0xffffffffu, s, off);
        float inv = 1.f / s;
        if (lane < S_) sc[r * SC_STR + lane] = roundtf(e0 * inv);
        sc[r * SC_STR + lane + 32] = roundtf(e1 * inv);
        if (lane + 64 < S_) sc[r * SC_STR + lane + 64] = roundtf(e2 * inv);
        if (lane + 96 < S_) sc[r * SC_STR + lane + 96] = roundtf(e3 * inv);
    }
    __syncthreads();

    // --- AV: warps 0..6; M-tile per warp, 8 n-tiles (N=64), K=104 (13 slices).
    if (warp < 7) {
        float acc[8][4];
#pragma unroll
        for (int ni = 0; ni < 8; ni++)
#pragma unroll
            for (int c = 0; c < 4; c++) acc[ni][c] = 0.f;
        const uint32_t* scu = (const uint32_t*)sc;
        const uint32_t* vsu = (const uint32_t*)vs;
        int m = warp * 16 + g;
#pragma unroll
        for (int ks = 0; ks < 13; ks++) {
            int k0 = ks * 8;
            uint32_t a[4];
            a[0] = scu[m * SC_STR + k0 + tg];
            a[1] = scu[(m + 8) * SC_STR + k0 + tg];
            a[2] = scu[m * SC_STR + k0 + tg + 4];
            a[3] = scu[(m + 8) * SC_STR + k0 + tg + 4];
#pragma unroll
            for (int ni = 0; ni < 8; ni++) {
                uint32_t bf[2];
                bf[0] = vsu[(k0 + tg) * VS_STR + ni * 8 + g];
                bf[1] = vsu[(k0 + tg + 4) * VS_STR + ni * 8 + g];
                mma_tf32(acc[ni], a, bf);
            }
        }
        const size_t cbase = (size_t)b * S_ * D_ + (size_t)h * DEPTH_;
#pragma unroll
        for (int ni = 0; ni < 8; ni++)
#pragma unroll
            for (int rr = 0; rr < 2; rr++) {
                int row = warp * 16 + rr * 8 + g;
                if (row < S_) {
                    int col = ni * 8 + tg * 2;
                    *(float2*)&ctx[cbase + (size_t)row * D_ + col] =
                        make_float2(roundtf(acc[ni][rr * 2]), roundtf(acc[ni][rr * 2 + 1]));
                }
            }
    }
}

// ---------------------------------------------------------------------------
// LayerNorm; optional tf32-rounded twin.
// ---------------------------------------------------------------------------
template <bool ROUND2>
__global__ __launch_bounds__(256)
void layernorm_kernel(const float* __restrict__ in, const float* __restrict__ gamma,
                      const float* __restrict__ beta, float* __restrict__ out,
                      float* __restrict__ out_r) {
    int row = blockIdx.x;
    const float* p = in + (size_t)row * D_;
    int tid = threadIdx.x;

    float vals[4];
    float sum = 0.f, sq = 0.f;
#pragma unroll
    for (int r = 0; r < 4; r++) {
        float v = p[tid + r * 256];
        vals[r] = v;
        sum += v;
        sq += v * v;
    }
#pragma unroll
    for (int off = 16; off > 0; off >>= 1) {
        sum += __shfl_xor_sync(0xffffffffu, sum, off);
        sq += __shfl_xor_sync(0xffffffffu, sq, off);
    }
    __shared__ float s1[8], s2[8];
    int wid = tid >> 5, lid = tid & 31;
    if (lid == 0) { s1[wid] = sum; s2[wid] = sq; }
    __syncthreads();
    if (wid == 0) {
        sum = (lid < 8) ? s1[lid] : 0.f;
        sq = (lid < 8) ? s2[lid] : 0.f;
#pragma unroll
        for (int off = 4; off > 0; off >>= 1) {
            sum += __shfl_xor_sync(0xffffffffu, sum, off);
            sq += __shfl_xor_sync(0xffffffffu, sq, off);
        }
        if (lid == 0) { s1[0] = sum; s2[0] = sq; }
    }
    __syncthreads();
    float mean = s1[0] * (1.0f / D_);
    float var = s2[0] * (1.0f / D_) - mean * mean;
    float inv = rsqrtf(var + EPS_);
#pragma unroll
    for (int r = 0; r < 4; r++) {
        int d = tid + r * 256;
        float o = gamma[d] * ((vals[r] - mean) * inv) + beta[d];
        out[(size_t)row * D_ + d] = o;
        if (ROUND2) out_r[(size_t)row * D_ + d] = roundtf(o);
    }
}

// ---------------------------------------------------------------------------
// Launch
// ---------------------------------------------------------------------------
extern "C" void kernel_launch(void* const* d_in, const int* in_sizes, int n_in,
                              void* d_out, int out_size) {
    const int* tokens = (const int*)d_in[0];
    const float* emb = (const float*)d_in[1];
    const float* Wq = (const float*)d_in[2];
    const float* bq = (const float*)d_in[3];
    const float* Wk = (const float*)d_in[4];
    const float* bk = (const float*)d_in[5];
    const float* Wv = (const float*)d_in[6];
    const float* bv = (const float*)d_in[7];
    const float* Wo = (const float*)d_in[8];
    const float* bo = (const float*)d_in[9];
    const float* W1 = (const float*)d_in[10];
    const float* b1 = (const float*)d_in[11];
    const float* W2 = (const float*)d_in[12];
    const float* b2 = (const float*)d_in[13];
    const float* gamma1 = (const float*)d_in[14];
    const float* beta1 = (const float*)d_in[15];
    const float* gamma2 = (const float*)d_in[16];
    const float* beta2 = (const float*)d_in[17];
    float* out = (float*)d_out;

    float *pe, *x, *xr, *Wqkv, *bqkv, *Wor, *W1r, *W2r, *QKV, *ctx, *t1, *x1, *x1r, *ffh;
    cudaGetSymbolAddress((void**)&pe, g_pe);
    cudaGetSymbolAddress((void**)&x, g_x);
    cudaGetSymbolAddress((void**)&xr, g_xr);
    cudaGetSymbolAddress((void**)&Wqkv, g_Wqkv);
    cudaGetSymbolAddress((void**)&bqkv, g_bqkv);
    cudaGetSymbolAddress((void**)&Wor, g_Wor);
    cudaGetSymbolAddress((void**)&W1r, g_W1r);
    cudaGetSymbolAddress((void**)&W2r, g_W2r);
    cudaGetSymbolAddress((void**)&QKV, g_QKV);
    cudaGetSymbolAddress((void**)&ctx, g_ctx);
    cudaGetSymbolAddress((void**)&t1, g_t1);
    cudaGetSymbolAddress((void**)&x1, g_x1);
    cudaGetSymbolAddress((void**)&x1r, g_x1r);
    cudaGetSymbolAddress((void**)&ffh, g_ffh);

    cudaFuncSetAttribute(attention_kernel,
                         cudaFuncAttributeMaxDynamicSharedMemorySize, ATT_SMEM);
    cudaFuncSetAttribute(mma_gemm<1>,
                         cudaFuncAttributeMaxDynamicSharedMemorySize, SMEM_GEMM);
    cudaFuncSetAttribute(mma_gemm<5>,
                         cudaFuncAttributeMaxDynamicSharedMemorySize, SMEM_GEMM);
    cudaFuncSetAttribute(mma_gemm<11>,
                         cudaFuncAttributeMaxDynamicSharedMemorySize, SMEM_GEMM);

    // 1. positional encoding + embedding (+ rounded twin)
    pe_kernel<<<(S_ * D_ + 255) / 256, 256>>>(pe);
    embed_kernel<<<(BS_ * D_ / 4 + 255) / 256, 256>>>(tokens, emb, pe, x, xr);

    // 2. weight prep (QKV permute + combined round-copies)
    permute_qkv_kernel<<<(3 * D_ * D_ + 255) / 256, 256>>>(Wq, Wk, Wv, bq, bk, bv,
                                                           Wqkv, bqkv);
    roundcpy3_kernel<<<(N4_WO + N4_W1 + N4_W2 + 255) / 256, 256>>>(Wo, Wor, W1, W1r,
                                                                   W2, W2r);

    // 3. fused QKV projection
    mma_gemm<1><<<dim3(N_QKV / 128, BS_ / 128), 128, SMEM_GEMM>>>(
        xr, Wqkv, QKV, bqkv, nullptr, BS_, N_QKV, D_);

    // 4. attention (tensor-core QK + AV; rounds ctx)
    attention_kernel<<<B_ * H_, 256, ATT_SMEM>>>(QKV, ctx);

    // 5. output projection + residual, LN1 (+rounded twin)
    mma_gemm<5><<<dim3(D_ / 128, BS_ / 128), 128, SMEM_GEMM>>>(
        ctx, Wor, t1, bo, x, BS_, D_, D_);
    layernorm_kernel<true><<<BS_, 256>>>(t1, gamma1, beta1, x1, x1r);

    // 6. FFN
    mma_gemm<11><<<dim3(F_ / 128, BS_ / 128), 128, SMEM_GEMM>>>(
        x1r, W1r, ffh, b1, nullptr, BS_, F_, D_);
    mma_gemm<5><<<dim3(D_ / 128, BS_ / 128), 128, SMEM_GEMM>>>(
        ffh, W2r, t1, b2, x1, BS_, D_, F_);

    // 7. LN2 -> output
    layernorm_kernel<false><<<BS_, 256>>>(t1, gamma2, beta2, out, nullptr);
}

// round 7
// speedup vs baseline: 4.3214x; 1.0075x over previous
#include <cuda_runtime.h>
#include <cuda_bf16.h>
#include <math.h>
#include <stdint.h>

// Problem constants
#define B_ 64
#define S_ 100
#define D_ 1024
#define H_ 16
#define F_ 4096
#define DEPTH_ 64
#define BS_ (B_ * S_)          // 6400
#define N_QKV 3072
#define EPS_ 1e-6f

// ---------------------------------------------------------------------------
// Scratch (device globals; no allocations allowed)
// ---------------------------------------------------------------------------
__device__ float g_pe[S_ * D_];
__device__ float g_x[BS_ * D_];      // full fp32 (residual path)
__device__ float g_xr[BS_ * D_];     // tf32-rounded (GEMM A operand)
__device__ float g_Wqkv[D_ * N_QKV]; // rounded, [K,N]
__device__ float g_bqkv[N_QKV];
__device__ float g_Wor[D_ * D_];     // rounded Wo [K,N]
__device__ float g_W1r[D_ * F_];     // rounded W1 [K,N]
__device__ float g_W2r[F_ * D_];     // rounded W2 [K,N]
__device__ float g_QKV[BS_ * N_QKV];
__device__ float g_ctx[BS_ * D_];    // rounded at attention epilogue
__device__ float g_t1[2 * BS_ * D_]; // split-K partial buffers
__device__ float g_x1[BS_ * D_];
__device__ float g_x1r[BS_ * D_];
__device__ float g_ffh[BS_ * F_];    // rounded at relu epilogue

__device__ __forceinline__ uint32_t f2tf32(float x) {
    uint32_t r;
    asm("cvt.rna.tf32.f32 %0, %1;" : "=r"(r) : "f"(x));
    return r;
}
__device__ __forceinline__ float roundtf(float x) {
    return __uint_as_float(f2tf32(x));
}

__device__ __forceinline__ void mma_tf32(float* d, const uint32_t* a, const uint32_t* b) {
    asm volatile(
        "mma.sync.aligned.m16n8k8.row.col.f32.tf32.tf32.f32 "
        "{%0,%1,%2,%3}, {%4,%5,%6,%7}, {%8,%9}, {%0,%1,%2,%3};\n"
        : "+f"(d[0]), "+f"(d[1]), "+f"(d[2]), "+f"(d[3])
        : "r"(a[0]), "r"(a[1]), "r"(a[2]), "r"(a[3]), "r"(b[0]), "r"(b[1]));
}

// ---------------------------------------------------------------------------
// Positional encoding (fp64 to match numpy float64 table)
// ---------------------------------------------------------------------------
__global__ void pe_kernel(float* __restrict__ pe) {
    int idx = blockIdx.x * blockDim.x + threadIdx.x;
    if (idx >= S_ * D_) return;
    int s = idx / D_;
    int d = idx % D_;
    int k2 = d & ~1;
    double div = pow(10000.0, (double)k2 / (double)D_);
    double arg = (double)s / div;
    pe[idx] = (float)((d & 1) ? cos(arg) : sin(arg));
}

// ---------------------------------------------------------------------------
// Embedding gather + positional add; writes fp32 x and tf32-rounded xr
// ---------------------------------------------------------------------------
__global__ void embed_kernel(const int* __restrict__ tokens,
                             const float* __restrict__ emb,
                             const float* __restrict__ pe,
                             float* __restrict__ x, float* __restrict__ xr) {
    int idx = blockIdx.x * blockDim.x + threadIdx.x;
    if (idx >= BS_ * D_ / 4) return;
    int row = idx / (D_ / 4);
    int c4 = idx % (D_ / 4);
    int tok = tokens[row];
    float4 e = ((const float4*)(emb + (size_t)tok * D_))[c4];
    float4 p = ((const float4*)(pe + (size_t)(row % S_) * D_))[c4];
    float4 o;
    o.x = e.x + p.x; o.y = e.y + p.y; o.z = e.z + p.z; o.w = e.w + p.w;
    ((float4*)x)[idx] = o;
    float4 r;
    r.x = roundtf(o.x); r.y = roundtf(o.y); r.z = roundtf(o.z); r.w = roundtf(o.w);
    ((float4*)xr)[idx] = r;
}

// ---------------------------------------------------------------------------
// Permute Wq/Wk/Wv [H,D,64] -> combined [D, 3072] (rounded); biases -> [3072]
// ---------------------------------------------------------------------------
__global__ void permute_qkv_kernel(const float* __restrict__ Wq, const float* __restrict__ Wk,
                                   const float* __restrict__ Wv,
                                   const float* __restrict__ bq, const float* __restrict__ bk,
                                   const float* __restrict__ bv,
                                   float* __restrict__ Wout, float* __restrict__ bout) {
    int idx = blockIdx.x * blockDim.x + threadIdx.x;
    const int total = 3 * D_ * D_;
    if (idx < total) {
        int which = idx / (D_ * D_);
        int r = idx % (D_ * D_);
        int d = r / D_;
        int n = r % D_;
        int h = n >> 6, e = n & 63;
        const float* W = (which == 0) ? Wq : ((which == 1) ? Wk : Wv);
        Wout[(size_t)d * N_QKV + which * D_ + n] =
            roundtf(W[((size_t)h * D_ + d) * DEPTH_ + e]);
    }
    if (idx < N_QKV) {
        int which = idx / D_;
        int n = idx % D_;
        const float* bb = (which == 0) ? bq : ((which == 1) ? bk : bv);
        bout[idx] = bb[n];
    }
}

// ---------------------------------------------------------------------------
// Combined tf32 round-copy of Wo, W1, W2 in one launch.
// ---------------------------------------------------------------------------
#define N4_WO (D_ * D_ / 4)
#define N4_W1 (D_ * F_ / 4)
#define N4_W2 (F_ * D_ / 4)
__global__ void roundcpy3_kernel(const float* __restrict__ Wo, float* __restrict__ WoR,
                                 const float* __restrict__ W1, float* __restrict__ W1R,
                                 const float* __restrict__ W2, float* __restrict__ W2R) {
    int idx = blockIdx.x * blockDim.x + threadIdx.x;
    const float* in;
    float* out;
    int off;
    if (idx < N4_WO) { in = Wo; out = WoR; off = idx; }
    else if (idx < N4_WO + N4_W1) { in = W1; out = W1R; off = idx - N4_WO; }
    else if (idx < N4_WO + N4_W1 + N4_W2) { in = W2; out = W2R; off = idx - N4_WO - N4_W1; }
    else return;
    float4 v = ((const float4*)in)[off];
    float4 r;
    r.x = roundtf(v.x); r.y = roundtf(v.y); r.z = roundtf(v.z); r.w = roundtf(v.w);
    ((float4*)out)[off] = r;
}

// ---------------------------------------------------------------------------
// TF32 mma.sync GEMM. 128x128 CTA tile, 4 warps of 64x64, k-step 32,
// cp.async double buffer. Split-K via gridDim.z: each z computes K/gridDim.z
// and writes its partial to C + z*M*N (EPI must be 0 when gridDim.z > 1).
// EPI: bit0 bias, bit1 relu, bit2 residual, bit3 round-output.
// ---------------------------------------------------------------------------
#define ASTRIDE 44
#define BSTRIDE 136
#define AFLOATS (128 * ASTRIDE)
#define BFLOATS (32 * BSTRIDE)
#define STAGEF  (AFLOATS + BFLOATS)
#define SMEM_GEMM (2 * STAGEF * 4)

template <int EPI>
__global__ __launch_bounds__(128, 2)
void mma_gemm(const float* __restrict__ A, const float* __restrict__ Bm,
              float* __restrict__ C, const float* __restrict__ bias,
              const float* __restrict__ res, int M, int N, int K) {
    extern __shared__ float smf[];
    int tid = threadIdx.x;
    int lane = tid & 31, warp = tid >> 5;
    int wm = warp & 1, wn = warp >> 1;
    int g = lane >> 2, tg = lane & 3;
    int bm = blockIdx.y * 128, bn = blockIdx.x * 128;

    // Split-K offsets
    int kspl = K / gridDim.z;
    int kOff = blockIdx.z * kspl;
    A += kOff;
    Bm += (size_t)kOff * N;
    C += (size_t)blockIdx.z * M * N;

    uint32_t smemBase = (uint32_t)__cvta_generic_to_shared(smf);

    float acc[4][8][4];
#pragma unroll
    for (int i = 0; i < 4; i++)
#pragma unroll
        for (int j = 0; j < 8; j++)
#pragma unroll
            for (int c = 0; c < 4; c++) acc[i][j][c] = 0.f;

    const int KT = kspl / 32;

    int aRow = tid >> 3, aColv = tid & 7;
    int bKrow = tid >> 5, bColv = tid & 31;
    const float* aSrc = A + (size_t)(bm + aRow) * K + aColv * 4;
    const float* bSrc = Bm + (size_t)bKrow * N + bn + bColv * 4;
    uint32_t aDst0 = smemBase + (uint32_t)(aRow * ASTRIDE + aColv * 4) * 4;
    uint32_t bDst0 = smemBase + AFLOATS * 4 + (uint32_t)(bKrow * BSTRIDE + bColv * 4) * 4;

    auto prefetch = [&](int stage) {
        uint32_t so = (uint32_t)(stage * STAGEF * 4);
#pragma unroll
        for (int q = 0; q < 8; q++) {
            uint32_t dst = aDst0 + so + (uint32_t)(q * 16 * ASTRIDE) * 4;
            const float* src = aSrc + (size_t)(q * 16) * K;
            asm volatile("cp.async.cg.shared.global [%0], [%1], 16;" :: "r"(dst), "l"(src));
        }
#pragma unroll
        for (int q = 0; q < 8; q++) {
            uint32_t dst = bDst0 + so + (uint32_t)(q * 4 * BSTRIDE) * 4;
            const float* src = bSrc + (size_t)(q * 4) * N;
            asm volatile("cp.async.cg.shared.global [%0], [%1], 16;" :: "r"(dst), "l"(src));
        }
        aSrc += 32;
        bSrc += (size_t)32 * N;
    };

    prefetch(0);
    asm volatile("cp.async.commit_group;");

    for (int kt = 0; kt < KT; kt++) {
        if (kt + 1 < KT) prefetch((kt + 1) & 1);
        asm volatile("cp.async.commit_group;");
        asm volatile("cp.async.wait_group 1;");
        __syncthreads();

        const uint32_t* As = (const uint32_t*)(smf + (kt & 1) * STAGEF);
        const uint32_t* Bs = As + AFLOATS;
#pragma unroll
        for (int ks = 0; ks < 4; ks++) {
            int k0 = ks * 8;
            uint32_t afr[4][4];
#pragma unroll
            for (int mi = 0; mi < 4; mi++) {
                int m = wm * 64 + mi * 16 + g;
                afr[mi][0] = As[m * ASTRIDE + k0 + tg];
                afr[mi][1] = As[(m + 8) * ASTRIDE + k0 + tg];
                afr[mi][2] = As[m * ASTRIDE + k0 + tg + 4];
                afr[mi][3] = As[(m + 8) * ASTRIDE + k0 + tg + 4];
            }
            uint32_t bfr[8][2];
#pragma unroll
            for (int ni = 0; ni < 8; ni++) {
                int n = wn * 64 + ni * 8 + g;
                bfr[ni][0] = Bs[(k0 + tg) * BSTRIDE + n];
                bfr[ni][1] = Bs[(k0 + tg + 4) * BSTRIDE + n];
            }
#pragma unroll
            for (int mi = 0; mi < 4; mi++)
#pragma unroll
                for (int ni = 0; ni < 8; ni++)
                    mma_tf32(acc[mi][ni], afr[mi], bfr[ni]);
        }
        __syncthreads();
    }

#pragma unroll
    for (int mi = 0; mi < 4; mi++) {
#pragma unroll
        for (int rr = 0; rr < 2; rr++) {
            int row = bm + wm * 64 + mi * 16 + rr * 8 + g;
#pragma unroll
            for (int ni = 0; ni < 8; ni++) {
                int col = bn + wn * 64 + ni * 8 + tg * 2;
                float vx = acc[mi][ni][rr * 2 + 0];
                float vy = acc[mi][ni][rr * 2 + 1];
                if (EPI & 1) { vx += bias[col]; vy += bias[col + 1]; }
                if (EPI & 4) {
                    const float* rp = res + (size_t)row * N + col;
                    vx += rp[0]; vy += rp[1];
                }
                if (EPI & 2) { vx = fmaxf(vx, 0.f); vy = fmaxf(vy, 0.f); }
                if (EPI & 8) { vx = roundtf(vx); vy = roundtf(vy); }
                *(float2*)&C[(size_t)row * N + col] = make_float2(vx, vy);
            }
        }
    }
}

// ---------------------------------------------------------------------------
// Fused attention per (b, h) — tensor-core QK^T and AV via mma.sync tf32.
// ---------------------------------------------------------------------------
#define QS_STR 76
#define KT_STR 104
#define VS_STR 72
#define SC_STR 108
#define QROWS 112
#define VROWS 104
#define SROWS 112
#define ATT_FLOATS (QROWS * QS_STR + DEPTH_ * KT_STR + VROWS * VS_STR + SROWS * SC_STR)
#define ATT_SMEM (ATT_FLOATS * 4)

__global__ __launch_bounds__(256)
void attention_kernel(const float* __restrict__ QKV, float* __restrict__ ctx) {
    extern __shared__ float sm[];
    float* qs = sm;
    float* kt = qs + QROWS * QS_STR;
    float* vs = kt + DEPTH_ * KT_STR;
    float* sc = vs + VROWS * VS_STR;

    int bh = blockIdx.x;
    int b = bh / H_;
    int h = bh % H_;
    int tid = threadIdx.x;
    int lane = tid & 31, warp = tid >> 5;
    int g = lane >> 2, tg = lane & 3;

    for (int i = tid; i < ATT_FLOATS; i += 256) sm[i] = 0.f;
    __syncthreads();

    for (int i = tid; i < S_ * (DEPTH_ / 4); i += 256) {
        int s = i >> 4, e4 = (i & 15) * 4;
        size_t off = ((size_t)(b * S_ + s)) * N_QKV + h * DEPTH_ + e4;
        float4 q = *(const float4*)(QKV + off);
        float4 k = *(const float4*)(QKV + off + D_);
        float4 v = *(const float4*)(QKV + off + 2 * D_);
        qs[s * QS_STR + e4 + 0] = roundtf(q.x);
        qs[s * QS_STR + e4 + 1] = roundtf(q.y);
        qs[s * QS_STR + e4 + 2] = roundtf(q.z);
        qs[s * QS_STR + e4 + 3] = roundtf(q.w);
        kt[(e4 + 0) * KT_STR + s] = roundtf(k.x);
        kt[(e4 + 1) * KT_STR + s] = roundtf(k.y);
        kt[(e4 + 2) * KT_STR + s] = roundtf(k.z);
        kt[(e4 + 3) * KT_STR + s] = roundtf(k.w);
        float4 vr = make_float4(roundtf(v.x), roundtf(v.y), roundtf(v.z), roundtf(v.w));
        *(float4*)&vs[s * VS_STR + e4] = vr;
    }
    __syncthreads();

    if (warp < 7) {
        float acc[13][4];
#pragma unroll
        for (int ni = 0; ni < 13; ni++)
#pragma unroll
            for (int c = 0; c < 4; c++) acc[ni][c] = 0.f;
        const uint32_t* qsu = (const uint32_t*)qs;
        const uint32_t* ktu = (const uint32_t*)kt;
        int m = warp * 16 + g;
#pragma unroll
        for (int ks = 0; ks < 8; ks++) {
            int k0 = ks * 8;
            uint32_t a[4];
            a[0] = qsu[m * QS_STR + k0 + tg];
            a[1] = qsu[(m + 8) * QS_STR + k0 + tg];
            a[2] = qsu[m * QS_STR + k0 + tg + 4];
            a[3] = qsu[(m + 8) * QS_STR + k0 + tg + 4];
#pragma unroll
            for (int ni = 0; ni < 13; ni++) {
                uint32_t bf[2];
                bf[0] = ktu[(k0 + tg) * KT_STR + ni * 8 + g];
                bf[1] = ktu[(k0 + tg + 4) * KT_STR + ni * 8 + g];
                mma_tf32(acc[ni], a, bf);
            }
        }
        const float scale = 0.125f;
#pragma unroll
        for (int ni = 0; ni < 13; ni++)
#pragma unroll
            for (int rr = 0; rr < 2; rr++) {
                int row = warp * 16 + rr * 8 + g;
                int col = ni * 8 + tg * 2;
                *(float2*)&sc[row * SC_STR + col] =
                    make_float2(acc[ni][rr * 2] * scale, acc[ni][rr * 2 + 1] * scale);
            }
    }
    __syncthreads();

    for (int r = warp; r < S_; r += 8) {
        float v0 = (lane < S_) ? sc[r * SC_STR + lane] : -1e30f;
        float v1 = sc[r * SC_STR + lane + 32];
        float v2 = (lane + 64 < S_) ? sc[r * SC_STR + lane + 64] : -1e30f;
        float v3 = (lane + 96 < S_) ? sc[r * SC_STR + lane + 96] : -1e30f;
        float m = fmaxf(fmaxf(v0, v1), fmaxf(v2, v3));
#pragma unroll
        for (int off = 16; off > 0; off >>= 1)
            m = fmaxf(m, __shfl_xor_sync(0xffffffffu, m, off));
        float e0 = (lane < S_) ? __expf(v0 - m) : 0.f;
        float e1 = __expf(v1 - m);
        float e2 = (lane + 64 < S_) ? __expf(v2 - m) : 0.f;
        float e3 = (lane + 96 < S_) ? __expf(v3 - m) : 0.f;
        float s = e0 + e1 + e2 + e3;
#pragma unroll
        for (int off = 16; off > 0; off >>= 1)
            s += __shfl_xor_sync(0xffffffffu, s, off);
        float inv = 1.f / s;
        if (lane < S_) sc[r * SC_STR + lane] = roundtf(e0 * inv);
        sc[r * SC_STR + lane + 32] = roundtf(e1 * inv);
        if (lane + 64 < S_) sc[r * SC_STR + lane + 64] = roundtf(e2 * inv);
        if (lane + 96 < S_) sc[r * SC_STR + lane + 96] = roundtf(e3 * inv);
    }
    __syncthreads();

    if (warp < 7) {
        float acc[8][4];
#pragma unroll
        for (int ni = 0; ni < 8; ni++)
#pragma unroll
            for (int c = 0; c < 4; c++) acc[ni][c] = 0.f;
        const uint32_t* scu = (const uint32_t*)sc;
        const uint32_t* vsu = (const uint32_t*)vs;
        int m = warp * 16 + g;
#pragma unroll
        for (int ks = 0; ks < 13; ks++) {
            int k0 = ks * 8;
            uint32_t a[4];
            a[0] = scu[m * SC_STR + k0 + tg];
            a[1] = scu[(m + 8) * SC_STR + k0 + tg];
            a[2] = scu[m * SC_STR + k0 + tg + 4];
            a[3] = scu[(m + 8) * SC_STR + k0 + tg + 4];
#pragma unroll
            for (int ni = 0; ni < 8; ni++) {
                uint32_t bf[2];
                bf[0] = vsu[(k0 + tg) * VS_STR + ni * 8 + g];
                bf[1] = vsu[(k0 + tg + 4) * VS_STR + ni * 8 + g];
                mma_tf32(acc[ni], a, bf);
            }
        }
        const size_t cbase = (size_t)b * S_ * D_ + (size_t)h * DEPTH_;
#pragma unroll
        for (int ni = 0; ni < 8; ni++)
#pragma unroll
            for (int rr = 0; rr < 2; rr++) {
                int row = warp * 16 + rr * 8 + g;
                if (row < S_) {
                    int col = ni * 8 + tg * 2;
                    *(float2*)&ctx[cbase + (size_t)row * D_ + col] =
                        make_float2(roundtf(acc[ni][rr * 2]), roundtf(acc[ni][rr * 2 + 1]));
                }
            }
    }
}

// ---------------------------------------------------------------------------
// Fused split-K reduce + bias + residual + LayerNorm.
// t = p0 + p1 + bias + res; out = LN(t); optional tf32-rounded twin.
// ---------------------------------------------------------------------------
template <bool ROUND2>
__global__ __launch_bounds__(256)
void lnred_kernel(const float* __restrict__ p0, const float* __restrict__ p1,
                  const float* __restrict__ bias, const float* __restrict__ res,
                  const float* __restrict__ gamma, const float* __restrict__ beta,
                  float* __restrict__ out, float* __restrict__ out_r) {
    int row = blockIdx.x;
    size_t base = (size_t)row * D_;
    int tid = threadIdx.x;

    float vals[4];
    float sum = 0.f, sq = 0.f;
#pragma unroll
    for (int r = 0; r < 4; r++) {
        int d = tid + r * 256;
        float v = p0[base + d] + p1[base + d] + bias[d] + res[base + d];
        vals[r] = v;
        sum += v;
        sq += v * v;
    }
#pragma unroll
    for (int off = 16; off > 0; off >>= 1) {
        sum += __shfl_xor_sync(0xffffffffu, sum, off);
        sq += __shfl_xor_sync(0xffffffffu, sq, off);
    }
    __shared__ float s1[8], s2[8];
    int wid = tid >> 5, lid = tid & 31;
    if (lid == 0) { s1[wid] = sum; s2[wid] = sq; }
    __syncthreads();
    if (wid == 0) {
        sum = (lid < 8) ? s1[lid] : 0.f;
        sq = (lid < 8) ? s2[lid] : 0.f;
#pragma unroll
        for (int off = 4; off > 0; off >>= 1) {
            sum += __shfl_xor_sync(0xffffffffu, sum, off);
            sq += __shfl_xor_sync(0xffffffffu, sq, off);
        }
        if (lid == 0) { s1[0] = sum; s2[0] = sq; }
    }
    __syncthreads();
    float mean = s1[0] * (1.0f / D_);
    float var = s2[0] * (1.0f / D_) - mean * mean;
    float inv = rsqrtf(var + EPS_);
#pragma unroll
    for (int r = 0; r < 4; r++) {
        int d = tid + r * 256;
        float o = gamma[d] * ((vals[r] - mean) * inv) + beta[d];
        out[base + d] = o;
        if (ROUND2) out_r[base + d] = roundtf(o);
    }
}

// ---------------------------------------------------------------------------
// Launch
// ---------------------------------------------------------------------------
extern "C" void kernel_launch(void* const* d_in, const int* in_sizes, int n_in,
                              void* d_out, int out_size) {
    const int* tokens = (const int*)d_in[0];
    const float* emb = (const float*)d_in[1];
    const float* Wq = (const float*)d_in[2];
    const float* bq = (const float*)d_in[3];
    const float* Wk = (const float*)d_in[4];
    const float* bk = (const float*)d_in[5];
    const float* Wv = (const float*)d_in[6];
    const float* bv = (const float*)d_in[7];
    const float* Wo = (const float*)d_in[8];
    const float* bo = (const float*)d_in[9];
    const float* W1 = (const float*)d_in[10];
    const float* b1 = (const float*)d_in[11];
    const float* W2 = (const float*)d_in[12];
    const float* b2 = (const float*)d_in[13];
    const float* gamma1 = (const float*)d_in[14];
    const float* beta1 = (const float*)d_in[15];
    const float* gamma2 = (const float*)d_in[16];
    const float* beta2 = (const float*)d_in[17];
    float* out = (float*)d_out;

    float *pe, *x, *xr, *Wqkv, *bqkv, *Wor, *W1r, *W2r, *QKV, *ctx, *t1, *x1, *x1r, *ffh;
    cudaGetSymbolAddress((void**)&pe, g_pe);
    cudaGetSymbolAddress((void**)&x, g_x);
    cudaGetSymbolAddress((void**)&xr, g_xr);
    cudaGetSymbolAddress((void**)&Wqkv, g_Wqkv);
    cudaGetSymbolAddress((void**)&bqkv, g_bqkv);
    cudaGetSymbolAddress((void**)&Wor, g_Wor);
    cudaGetSymbolAddress((void**)&W1r, g_W1r);
    cudaGetSymbolAddress((void**)&W2r, g_W2r);
    cudaGetSymbolAddress((void**)&QKV, g_QKV);
    cudaGetSymbolAddress((void**)&ctx, g_ctx);
    cudaGetSymbolAddress((void**)&t1, g_t1);
    cudaGetSymbolAddress((void**)&x1, g_x1);
    cudaGetSymbolAddress((void**)&x1r, g_x1r);
    cudaGetSymbolAddress((void**)&ffh, g_ffh);

    cudaFuncSetAttribute(attention_kernel,
                         cudaFuncAttributeMaxDynamicSharedMemorySize, ATT_SMEM);
    cudaFuncSetAttribute(mma_gemm<0>,
                         cudaFuncAttributeMaxDynamicSharedMemorySize, SMEM_GEMM);
    cudaFuncSetAttribute(mma_gemm<1>,
                         cudaFuncAttributeMaxDynamicSharedMemorySize, SMEM_GEMM);
    cudaFuncSetAttribute(mma_gemm<11>,
                         cudaFuncAttributeMaxDynamicSharedMemorySize, SMEM_GEMM);

    // 1. positional encoding + embedding (+ rounded twin)
    pe_kernel<<<(S_ * D_ + 255) / 256, 256>>>(pe);
    embed_kernel<<<(BS_ * D_ / 4 + 255) / 256, 256>>>(tokens, emb, pe, x, xr);

    // 2. weight prep
    permute_qkv_kernel<<<(3 * D_ * D_ + 255) / 256, 256>>>(Wq, Wk, Wv, bq, bk, bv,
                                                           Wqkv, bqkv);
    roundcpy3_kernel<<<(N4_WO + N4_W1 + N4_W2 + 255) / 256, 256>>>(Wo, Wor, W1, W1r,
                                                                   W2, W2r);

    // 3. fused QKV projection
    mma_gemm<1><<<dim3(N_QKV / 128, BS_ / 128), 128, SMEM_GEMM>>>(
        xr, Wqkv, QKV, bqkv, nullptr, BS_, N_QKV, D_);

    // 4. attention (tensor-core QK + AV; rounds ctx)
    attention_kernel<<<B_ * H_, 256, ATT_SMEM>>>(QKV, ctx);

    // 5. output projection (split-K 2, raw partials) + fused reduce+LN1
    mma_gemm<0><<<dim3(D_ / 128, BS_ / 128, 2), 128, SMEM_GEMM>>>(
        ctx, Wor, t1, nullptr, nullptr, BS_, D_, D_);
    lnred_kernel<true><<<BS_, 256>>>(t1, t1 + (size_t)BS_ * D_, bo, x,
                                     gamma1, beta1, x1, x1r);

    // 6. FFN: W1 (bias+relu+round epilogue), W2 (split-K 2, raw partials)
    mma_gemm<11><<<dim3(F_ / 128, BS_ / 128), 128, SMEM_GEMM>>>(
        x1r, W1r, ffh, b1, nullptr, BS_, F_, D_);
    mma_gemm<0><<<dim3(D_ / 128, BS_ / 128, 2), 128, SMEM_GEMM>>>(
        ffh, W2r, t1, nullptr, nullptr, BS_, D_, F_);

    // 7. fused reduce + LN2 -> output
    lnred_kernel<false><<<BS_, 256>>>(t1, t1 + (size_t)BS_ * D_, b2, x1,
                                      gamma2, beta2, out, nullptr);
}